// round 1
// baseline (speedup 1.0000x reference)
#include <cuda_runtime.h>
#include <math.h>

#define B_  2
#define N_  2048
#define NC_ 128
#define D_  2048
#define H_  16
#define DH_ 128
#define L_  (N_ + NC_)     // 2176
#define D3_ (3 * D_)       // 6144

// ---------------- scratch (device globals; no allocations allowed) ----------
__device__ float g_Q[(size_t)B_ * H_ * L_ * DH_];   // (b,h,l,dh)
__device__ float g_K[(size_t)B_ * H_ * L_ * DH_];
__device__ float g_V[(size_t)B_ * H_ * L_ * DH_];
__device__ float g_O[(size_t)B_ * N_ * D_];         // (b,n,d) attention output

// ---------------- SGEMM: C[m][n] = sum_k A[m][k] * W[n][k] ------------------
// BM=BN=128, BK=8, 256 threads, 8x8 microtile.
// MODE 0: A=x (4096xK), scatter into g_Q/g_K/g_V at l=n
// MODE 1: A=c (256xK),  scatter into g_Q/g_K/g_V at l=N_+n
// MODE 2: A=g_O,        out[m][n] = acc + bias[n]
template <int MODE>
__global__ __launch_bounds__(256, 2)
void gemm_k(const float* __restrict__ A, const float* __restrict__ W,
            const float* __restrict__ bias, float* __restrict__ out)
{
    constexpr int K = D_;
    __shared__ float sA[8][132];
    __shared__ float sB[8][132];

    const int n0 = blockIdx.x * 128;
    const int m0 = blockIdx.y * 128;
    const int t  = threadIdx.x;
    const int tx = t & 15, ty = t >> 4;
    const int lr = t >> 1;           // row within tile for loads
    const int lk = (t & 1) * 4;      // k offset 0 or 4

    const float* Aptr = (MODE == 2) ? g_O : A;

    float acc[8][8];
#pragma unroll
    for (int i = 0; i < 8; i++)
#pragma unroll
        for (int j = 0; j < 8; j++) acc[i][j] = 0.0f;

    for (int kt = 0; kt < K; kt += 8) {
        float4 a4 = *(const float4*)(Aptr + (size_t)(m0 + lr) * K + kt + lk);
        float4 b4 = *(const float4*)(W    + (size_t)(n0 + lr) * K + kt + lk);
        __syncthreads();
        sA[lk + 0][lr] = a4.x; sA[lk + 1][lr] = a4.y;
        sA[lk + 2][lr] = a4.z; sA[lk + 3][lr] = a4.w;
        sB[lk + 0][lr] = b4.x; sB[lk + 1][lr] = b4.y;
        sB[lk + 2][lr] = b4.z; sB[lk + 3][lr] = b4.w;
        __syncthreads();
#pragma unroll
        for (int kk = 0; kk < 8; kk++) {
            float4 a0 = *(const float4*)&sA[kk][ty * 4];
            float4 a1 = *(const float4*)&sA[kk][64 + ty * 4];
            float4 b0 = *(const float4*)&sB[kk][tx * 4];
            float4 b1 = *(const float4*)&sB[kk][64 + tx * 4];
            float af[8] = {a0.x, a0.y, a0.z, a0.w, a1.x, a1.y, a1.z, a1.w};
            float bf[8] = {b0.x, b0.y, b0.z, b0.w, b1.x, b1.y, b1.z, b1.w};
#pragma unroll
            for (int i = 0; i < 8; i++)
#pragma unroll
                for (int j = 0; j < 8; j++) acc[i][j] += af[i] * bf[j];
        }
    }

    if (MODE == 0 || MODE == 1) {
        // column tile maps to exactly one (part, head): D3 tiles of 128 == DH
        const int part = n0 >> 11;            // 0=q 1=k 2=v
        const int hh   = (n0 & 2047) >> 7;    // head
        float* dst = (part == 0) ? g_Q : (part == 1) ? g_K : g_V;
        const int rdiv = (MODE == 0) ? N_ : NC_;
#pragma unroll
        for (int i = 0; i < 8; i++) {
            int m = m0 + ((i < 4) ? (ty * 4 + i) : (64 + ty * 4 + i - 4));
            int b = m / rdiv, n = m % rdiv;
            int l = (MODE == 0) ? n : (N_ + n);
            float* rowp = dst + ((size_t)(b * H_ + hh) * L_ + l) * DH_;
#pragma unroll
            for (int j = 0; j < 8; j++) {
                int dh = (j < 4) ? (tx * 4 + j) : (64 + tx * 4 + j - 4);
                rowp[dh] = acc[i][j];
            }
        }
    } else {
#pragma unroll
        for (int i = 0; i < 8; i++) {
            int m = m0 + ((i < 4) ? (ty * 4 + i) : (64 + ty * 4 + i - 4));
#pragma unroll
            for (int j = 0; j < 8; j++) {
                int nj = n0 + ((j < 4) ? (tx * 4 + j) : (64 + tx * 4 + j - 4));
                out[(size_t)m * D_ + nj] = acc[i][j] + bias[nj];
            }
        }
    }
}

// ---------------- L2-norm + learned scale + RoPE on Q and K -----------------
__global__ __launch_bounds__(128)
void normrope_k(const float* __restrict__ scale, const float* __restrict__ cscale)
{
    const int l = blockIdx.x, h = blockIdx.y, b = blockIdx.z;
    const int tid = threadIdx.x;
    __shared__ float buf[128];
    __shared__ float red[4];

    const size_t rbase = ((size_t)(b * H_ + h) * L_ + l) * DH_;
    const float* scp = (l < N_) ? scale : cscale;
    const float sc = scp[h * DH_ + tid] * 45.25483399593904f;  // sqrt(2048)

    // RoPE coefficients: angle computed as f32 product (matches jnp), trig in fp64
    const int i = tid & 63;
    const float invf = (float)(1.0 / pow(10000.0, (double)i / 64.0));
    const float ang  = (float)l * invf;
    const float cs = (float)cos((double)ang);
    const float sn = (float)sin((double)ang);

#pragma unroll
    for (int which = 0; which < 2; which++) {
        float* ptr = ((which == 0) ? g_Q : g_K) + rbase;
        float v = ptr[tid];
        float ss = v * v;
#pragma unroll
        for (int o = 16; o > 0; o >>= 1) ss += __shfl_xor_sync(0xffffffffu, ss, o);
        if ((tid & 31) == 0) red[tid >> 5] = ss;
        __syncthreads();
        float tot = red[0] + red[1] + red[2] + red[3];
        float inv = 1.0f / fmaxf(sqrtf(tot), 1e-12f);
        buf[tid] = v * inv * sc;
        __syncthreads();
        float o;
        if (tid < 64) { float x1 = buf[tid],      x2 = buf[tid + 64]; o = x1 * cs - x2 * sn; }
        else          { float x1 = buf[tid - 64], x2 = buf[tid];      o = x1 * sn + x2 * cs; }
        ptr[tid] = o;
        __syncthreads();
    }
}

// ---------------- flash-style attention -------------------------------------
// Block: 64 queries x 128 dh, loop over 34 key tiles of 64. 256 threads.
#define SMQ 129
#define SMK 129
#define SMV 128
#define SMP 65
#define ATTN_SMEM ((64 * SMQ + 64 * SMK + 64 * SMV + 64 * SMP) * 4)

__global__ __launch_bounds__(256)
void attn_k()
{
    extern __shared__ float sm[];
    float* sQ = sm;
    float* sK = sQ + 64 * SMQ;
    float* sV = sK + 64 * SMK;
    float* sP = sV + 64 * SMV;

    const int qt = blockIdx.x, h = blockIdx.y, b = blockIdx.z;
    const int t = threadIdx.x, tx = t & 15, ty = t >> 4;
    const size_t base = (size_t)(b * H_ + h) * L_ * DH_;
    const int q0 = qt * 64;

    for (int i = t; i < 64 * 32; i += 256) {
        int r = i >> 5, c = (i & 31) << 2;
        float4 v = *(const float4*)(g_Q + base + (size_t)(q0 + r) * DH_ + c);
        sQ[r * SMQ + c + 0] = v.x; sQ[r * SMQ + c + 1] = v.y;
        sQ[r * SMQ + c + 2] = v.z; sQ[r * SMQ + c + 3] = v.w;
    }

    float acc[4][8];
    float mrow[4], lrow[4];
#pragma unroll
    for (int i = 0; i < 4; i++) {
        mrow[i] = -INFINITY; lrow[i] = 0.0f;
#pragma unroll
        for (int j = 0; j < 8; j++) acc[i][j] = 0.0f;
    }

    const float smscale = 0.08838834764831845f;  // 1/sqrt(128)

    for (int kt = 0; kt < L_ / 64; kt++) {
        const int k0 = kt * 64;
        __syncthreads();
        for (int i = t; i < 64 * 32; i += 256) {
            int r = i >> 5, c = (i & 31) << 2;
            float4 kv = *(const float4*)(g_K + base + (size_t)(k0 + r) * DH_ + c);
            sK[r * SMK + c + 0] = kv.x; sK[r * SMK + c + 1] = kv.y;
            sK[r * SMK + c + 2] = kv.z; sK[r * SMK + c + 3] = kv.w;
            float4 vv = *(const float4*)(g_V + base + (size_t)(k0 + r) * DH_ + c);
            *(float4*)&sV[r * SMV + c] = vv;
        }
        __syncthreads();

        float s[4][4];
#pragma unroll
        for (int i = 0; i < 4; i++)
#pragma unroll
            for (int j = 0; j < 4; j++) s[i][j] = 0.0f;

#pragma unroll 4
        for (int d = 0; d < 128; d++) {
            float qf[4], kf[4];
#pragma unroll
            for (int i = 0; i < 4; i++) qf[i] = sQ[(ty * 4 + i) * SMQ + d];
#pragma unroll
            for (int j = 0; j < 4; j++) kf[j] = sK[(tx * 4 + j) * SMK + d];
#pragma unroll
            for (int i = 0; i < 4; i++)
#pragma unroll
                for (int j = 0; j < 4; j++) s[i][j] += qf[i] * kf[j];
        }

#pragma unroll
        for (int i = 0; i < 4; i++) {
            float mx = -INFINITY;
#pragma unroll
            for (int j = 0; j < 4; j++) { s[i][j] *= smscale; mx = fmaxf(mx, s[i][j]); }
#pragma unroll
            for (int o = 1; o < 16; o <<= 1)
                mx = fmaxf(mx, __shfl_xor_sync(0xffffffffu, mx, o));
            float mn = fmaxf(mrow[i], mx);
            float sum = 0.0f;
#pragma unroll
            for (int j = 0; j < 4; j++) {
                float p = __expf(s[i][j] - mn);
                sP[(ty * 4 + i) * SMP + tx * 4 + j] = p;
                sum += p;
            }
#pragma unroll
            for (int o = 1; o < 16; o <<= 1)
                sum += __shfl_xor_sync(0xffffffffu, sum, o);
            float r = __expf(mrow[i] - mn);
            mrow[i] = mn;
            lrow[i] = lrow[i] * r + sum;
#pragma unroll
            for (int j = 0; j < 8; j++) acc[i][j] *= r;
        }
        __syncthreads();

#pragma unroll 2
        for (int k = 0; k < 64; k++) {
            float pv[4], vv[8];
#pragma unroll
            for (int i = 0; i < 4; i++) pv[i] = sP[(ty * 4 + i) * SMP + k];
#pragma unroll
            for (int j = 0; j < 8; j++) vv[j] = sV[k * SMV + j * 16 + tx];
#pragma unroll
            for (int i = 0; i < 4; i++)
#pragma unroll
                for (int j = 0; j < 8; j++) acc[i][j] += pv[i] * vv[j];
        }
    }

#pragma unroll
    for (int i = 0; i < 4; i++) {
        float inv = 1.0f / lrow[i];
        float* op = g_O + ((size_t)b * N_ + q0 + ty * 4 + i) * D_ + h * DH_;
#pragma unroll
        for (int j = 0; j < 8; j++) op[j * 16 + tx] = acc[i][j] * inv;
    }
}

// ---------------- launch -----------------------------------------------------
extern "C" void kernel_launch(void* const* d_in, const int* in_sizes, int n_in,
                              void* d_out, int out_size)
{
    const float* x    = (const float*)d_in[0];
    const float* c    = (const float*)d_in[1];
    const float* wqkv = (const float*)d_in[2];
    const float* wcq  = (const float*)d_in[3];
    const float* wo   = (const float*)d_in[4];
    const float* bo   = (const float*)d_in[5];
    const float* sc   = (const float*)d_in[6];
    const float* csc  = (const float*)d_in[7];
    float* out = (float*)d_out;

    // self + cross QKV projections (scatter into (b,h,l,dh) with concat offset)
    gemm_k<0><<<dim3(D3_ / 128, (B_ * N_) / 128), 256>>>(x, wqkv, nullptr, nullptr);
    gemm_k<1><<<dim3(D3_ / 128, (B_ * NC_) / 128), 256>>>(c, wcq, nullptr, nullptr);

    // L2-norm + scale + RoPE on Q/K
    normrope_k<<<dim3(L_, H_, B_), 128>>>(sc, csc);

    // attention
    cudaFuncSetAttribute(attn_k, cudaFuncAttributeMaxDynamicSharedMemorySize, ATTN_SMEM);
    attn_k<<<dim3(N_ / 64, H_, B_), 256, ATTN_SMEM>>>();

    // output projection + bias
    gemm_k<2><<<dim3(D_ / 128, (B_ * N_) / 128), 256>>>(nullptr, wo, bo, out);
}

// round 3
// speedup vs baseline: 1.2069x; 1.2069x over previous
#include <cuda_runtime.h>
#include <cstdint>
#include <math.h>

#define B_  2
#define N_  2048
#define NC_ 128
#define D_  2048
#define H_  16
#define DH_ 128
#define L_  (N_ + NC_)     // 2176
#define D3_ (3 * D_)       // 6144

// ---------------- scratch (device globals; no allocations allowed) ----------
__device__ float g_Q[(size_t)B_ * H_ * L_ * DH_];   // (b,h,l,dh)
__device__ float g_K[(size_t)B_ * H_ * L_ * DH_];
__device__ float g_V[(size_t)B_ * H_ * L_ * DH_];
__device__ float g_O[(size_t)B_ * N_ * D_];         // (b,n,d) attention output

__device__ __forceinline__ float to_tf32(float x) {
    float r; asm("cvt.rna.tf32.f32 %0, %1;" : "=f"(r) : "f"(x)); return r;
}

// mma.sync m16n8k8 tf32: D += A*B  (row.col)
__device__ __forceinline__ void mma_tf32(float* d, const uint32_t* a, const uint32_t* b) {
    asm volatile(
        "mma.sync.aligned.m16n8k8.row.col.f32.tf32.tf32.f32 "
        "{%0,%1,%2,%3},{%4,%5,%6,%7},{%8,%9},{%0,%1,%2,%3};"
        : "+f"(d[0]), "+f"(d[1]), "+f"(d[2]), "+f"(d[3])
        : "r"(a[0]), "r"(a[1]), "r"(a[2]), "r"(a[3]), "r"(b[0]), "r"(b[1]));
}

// ================= tf32 mma GEMM: C[m][n] = sum_k A[m][k] W[n][k] ===========
// 128x128 CTA tile, BK=16 double-buffered, 8 warps of 64x32.
// MODE 0: A=x, scatter into g_Q/g_K/g_V at l=n      (rows = b*N_+n)
// MODE 1: A=c, scatter into g_Q/g_K/g_V at l=N_+n   (rows = b*NC_+n)
// MODE 2: A=g_O, out[m][n] = acc + bias[n]
#define KSLAB 16
#define SSTR  136                      // smem row stride (floats), conflict-free
#define GEMM_SMEM (2 * 2 * KSLAB * SSTR * 4)   // A+B, double buffered

template <int MODE>
__global__ __launch_bounds__(256, 2)
void gemm_mma(const float* __restrict__ A, const float* __restrict__ W,
              const float* __restrict__ bias, float* __restrict__ out)
{
    constexpr int K = D_;
    constexpr int NS = K / KSLAB;      // 128 slabs
    extern __shared__ float sm[];
    float* As = sm;                     // [2][16][136] k-major
    float* Bs = sm + 2 * KSLAB * SSTR;

    const int t = threadIdx.x;
    const int wid = t >> 5, lane = t & 31;
    const int g = lane >> 2, tig = lane & 3;
    const int wm = (wid >> 2) * 64;     // warp m offset (0/64)
    const int wn = (wid & 3) * 32;      // warp n offset
    const int n0 = blockIdx.x * 128;
    const int m0 = blockIdx.y * 128;

    const float* Ag = (MODE == 2) ? g_O : A;
    const int lrow = t & 127;           // tile row handled by this thread
    const int lc   = (t >> 7) * 8;      // k sub-offset 0 or 8

    const float* aptr = Ag + (size_t)(m0 + lrow) * K + lc;
    const float* bptr = W  + (size_t)(n0 + lrow) * K + lc;

    float acc[4][4][4];
#pragma unroll
    for (int mi = 0; mi < 4; mi++)
#pragma unroll
        for (int ni = 0; ni < 4; ni++)
#pragma unroll
            for (int r = 0; r < 4; r++) acc[mi][ni][r] = 0.0f;

    float ra[8], rb[8];

    // prologue: slab 0
    {
        float4 a0 = *(const float4*)(aptr);
        float4 a1 = *(const float4*)(aptr + 4);
        float4 b0 = *(const float4*)(bptr);
        float4 b1 = *(const float4*)(bptr + 4);
        ra[0]=a0.x; ra[1]=a0.y; ra[2]=a0.z; ra[3]=a0.w; ra[4]=a1.x; ra[5]=a1.y; ra[6]=a1.z; ra[7]=a1.w;
        rb[0]=b0.x; rb[1]=b0.y; rb[2]=b0.z; rb[3]=b0.w; rb[4]=b1.x; rb[5]=b1.y; rb[6]=b1.z; rb[7]=b1.w;
#pragma unroll
        for (int j = 0; j < 8; j++) {
            As[(lc + j) * SSTR + lrow] = to_tf32(ra[j]);
            Bs[(lc + j) * SSTR + lrow] = to_tf32(rb[j]);
        }
    }

    for (int kt = 0; kt < NS; kt++) {
        __syncthreads();
        const int buf = kt & 1;
        if (kt + 1 < NS) {
            const float* ap = aptr + (size_t)(kt + 1) * KSLAB;
            const float* bp = bptr + (size_t)(kt + 1) * KSLAB;
            float4 a0 = *(const float4*)(ap);
            float4 a1 = *(const float4*)(ap + 4);
            float4 b0 = *(const float4*)(bp);
            float4 b1 = *(const float4*)(bp + 4);
            ra[0]=a0.x; ra[1]=a0.y; ra[2]=a0.z; ra[3]=a0.w; ra[4]=a1.x; ra[5]=a1.y; ra[6]=a1.z; ra[7]=a1.w;
            rb[0]=b0.x; rb[1]=b0.y; rb[2]=b0.z; rb[3]=b0.w; rb[4]=b1.x; rb[5]=b1.y; rb[6]=b1.z; rb[7]=b1.w;
        }

        const uint32_t* ab = (const uint32_t*)(As + buf * KSLAB * SSTR);
        const uint32_t* bb = (const uint32_t*)(Bs + buf * KSLAB * SSTR);
#pragma unroll
        for (int ks = 0; ks < 2; ks++) {
            const int k = ks * 8;
            uint32_t bf[4][2];
#pragma unroll
            for (int ni = 0; ni < 4; ni++) {
                const int n = wn + ni * 8 + g;
                bf[ni][0] = bb[(k + tig) * SSTR + n];
                bf[ni][1] = bb[(k + 4 + tig) * SSTR + n];
            }
#pragma unroll
            for (int mi = 0; mi < 4; mi++) {
                const int m = wm + mi * 16 + g;
                uint32_t af[4];
                af[0] = ab[(k + tig) * SSTR + m];
                af[1] = ab[(k + tig) * SSTR + m + 8];
                af[2] = ab[(k + 4 + tig) * SSTR + m];
                af[3] = ab[(k + 4 + tig) * SSTR + m + 8];
#pragma unroll
                for (int ni = 0; ni < 4; ni++)
                    mma_tf32(acc[mi][ni], af, bf[ni]);
            }
        }

        if (kt + 1 < NS) {
            float* ad = As + ((kt + 1) & 1) * KSLAB * SSTR;
            float* bd = Bs + ((kt + 1) & 1) * KSLAB * SSTR;
#pragma unroll
            for (int j = 0; j < 8; j++) {
                ad[(lc + j) * SSTR + lrow] = to_tf32(ra[j]);
                bd[(lc + j) * SSTR + lrow] = to_tf32(rb[j]);
            }
        }
    }

    // -------- epilogue: c0/c1 at (row g, cols 2tig,2tig+1), c2/c3 at row g+8
    if (MODE == 0 || MODE == 1) {
        const int part = n0 >> 11;            // 0=q 1=k 2=v
        const int hh   = (n0 & 2047) >> 7;    // head
        float* dst = (part == 0) ? g_Q : (part == 1) ? g_K : g_V;
#pragma unroll
        for (int mi = 0; mi < 4; mi++) {
#pragma unroll
            for (int hi = 0; hi < 2; hi++) {
                const int m = m0 + wm + mi * 16 + g + hi * 8;
                int b, l;
                if (MODE == 0) { b = m >> 11; l = m & 2047; }
                else           { b = m >> 7;  l = N_ + (m & 127); }
                float* rowp = dst + ((size_t)(b * H_ + hh) * L_ + l) * DH_;
#pragma unroll
                for (int ni = 0; ni < 4; ni++) {
                    const int dh = wn + ni * 8 + 2 * tig;
                    *(float2*)(rowp + dh) = make_float2(acc[mi][ni][hi * 2], acc[mi][ni][hi * 2 + 1]);
                }
            }
        }
    } else {
#pragma unroll
        for (int mi = 0; mi < 4; mi++) {
#pragma unroll
            for (int hi = 0; hi < 2; hi++) {
                const int m = m0 + wm + mi * 16 + g + hi * 8;
                float* op = out + (size_t)m * D_;
#pragma unroll
                for (int ni = 0; ni < 4; ni++) {
                    const int n = n0 + wn + ni * 8 + 2 * tig;
                    *(float2*)(op + n) = make_float2(acc[mi][ni][hi * 2] + bias[n],
                                                     acc[mi][ni][hi * 2 + 1] + bias[n + 1]);
                }
            }
        }
    }
}

// ---------------- L2-norm + learned scale + RoPE on Q and K -----------------
__global__ __launch_bounds__(128)
void normrope_k(const float* __restrict__ scale, const float* __restrict__ cscale)
{
    const int l = blockIdx.x, h = blockIdx.y, b = blockIdx.z;
    const int tid = threadIdx.x;
    __shared__ float buf[128];
    __shared__ float red[4];

    const size_t rbase = ((size_t)(b * H_ + h) * L_ + l) * DH_;
    const float* scp = (l < N_) ? scale : cscale;
    const float sc = scp[h * DH_ + tid] * 45.25483399593904f;  // sqrt(2048)

    const int i = tid & 63;
    const float invf = (float)(1.0 / pow(10000.0, (double)i / 64.0));
    const float ang  = (float)l * invf;
    const float cs = (float)cos((double)ang);
    const float sn = (float)sin((double)ang);

#pragma unroll
    for (int which = 0; which < 2; which++) {
        float* ptr = ((which == 0) ? g_Q : g_K) + rbase;
        float v = ptr[tid];
        float ss = v * v;
#pragma unroll
        for (int o = 16; o > 0; o >>= 1) ss += __shfl_xor_sync(0xffffffffu, ss, o);
        if ((tid & 31) == 0) red[tid >> 5] = ss;
        __syncthreads();
        float tot = red[0] + red[1] + red[2] + red[3];
        float inv = 1.0f / fmaxf(sqrtf(tot), 1e-12f);
        buf[tid] = v * inv * sc;
        __syncthreads();
        float o;
        if (tid < 64) { float x1 = buf[tid],      x2 = buf[tid + 64]; o = x1 * cs - x2 * sn; }
        else          { float x1 = buf[tid - 64], x2 = buf[tid];      o = x1 * sn + x2 * cs; }
        ptr[tid] = o;
        __syncthreads();
    }
}

// ---------------- flash-style attention (fp32 SIMT) --------------------------
#define SMQ 129
#define SMK 129
#define SMV 128
#define SMP 65
#define ATTN_SMEM ((64 * SMQ + 64 * SMK + 64 * SMV + 64 * SMP) * 4)

__global__ __launch_bounds__(256)
void attn_k()
{
    extern __shared__ float sm[];
    float* sQ = sm;
    float* sK = sQ + 64 * SMQ;
    float* sV = sK + 64 * SMK;
    float* sP = sV + 64 * SMV;

    const int qt = blockIdx.x, h = blockIdx.y, b = blockIdx.z;
    const int t = threadIdx.x, tx = t & 15, ty = t >> 4;
    const size_t base = (size_t)(b * H_ + h) * L_ * DH_;
    const int q0 = qt * 64;

    for (int i = t; i < 64 * 32; i += 256) {
        int r = i >> 5, c = (i & 31) << 2;
        float4 v = *(const float4*)(g_Q + base + (size_t)(q0 + r) * DH_ + c);
        sQ[r * SMQ + c + 0] = v.x; sQ[r * SMQ + c + 1] = v.y;
        sQ[r * SMQ + c + 2] = v.z; sQ[r * SMQ + c + 3] = v.w;
    }

    float acc[4][8];
    float mrow[4], lrow[4];
#pragma unroll
    for (int i = 0; i < 4; i++) {
        mrow[i] = -INFINITY; lrow[i] = 0.0f;
#pragma unroll
        for (int j = 0; j < 8; j++) acc[i][j] = 0.0f;
    }

    const float smscale = 0.08838834764831845f;  // 1/sqrt(128)

    for (int kt = 0; kt < L_ / 64; kt++) {
        const int k0 = kt * 64;
        __syncthreads();
        for (int i = t; i < 64 * 32; i += 256) {
            int r = i >> 5, c = (i & 31) << 2;
            float4 kv = *(const float4*)(g_K + base + (size_t)(k0 + r) * DH_ + c);
            sK[r * SMK + c + 0] = kv.x; sK[r * SMK + c + 1] = kv.y;
            sK[r * SMK + c + 2] = kv.z; sK[r * SMK + c + 3] = kv.w;
            float4 vv = *(const float4*)(g_V + base + (size_t)(k0 + r) * DH_ + c);
            *(float4*)&sV[r * SMV + c] = vv;
        }
        __syncthreads();

        float s[4][4];
#pragma unroll
        for (int i = 0; i < 4; i++)
#pragma unroll
            for (int j = 0; j < 4; j++) s[i][j] = 0.0f;

#pragma unroll 4
        for (int d = 0; d < 128; d++) {
            float qf[4], kf[4];
#pragma unroll
            for (int i = 0; i < 4; i++) qf[i] = sQ[(ty * 4 + i) * SMQ + d];
#pragma unroll
            for (int j = 0; j < 4; j++) kf[j] = sK[(tx * 4 + j) * SMK + d];
#pragma unroll
            for (int i = 0; i < 4; i++)
#pragma unroll
                for (int j = 0; j < 4; j++) s[i][j] += qf[i] * kf[j];
        }

#pragma unroll
        for (int i = 0; i < 4; i++) {
            float mx = -INFINITY;
#pragma unroll
            for (int j = 0; j < 4; j++) { s[i][j] *= smscale; mx = fmaxf(mx, s[i][j]); }
#pragma unroll
            for (int o = 1; o < 16; o <<= 1)
                mx = fmaxf(mx, __shfl_xor_sync(0xffffffffu, mx, o));
            float mn = fmaxf(mrow[i], mx);
            float sum = 0.0f;
#pragma unroll
            for (int j = 0; j < 4; j++) {
                float p = __expf(s[i][j] - mn);
                sP[(ty * 4 + i) * SMP + tx * 4 + j] = p;
                sum += p;
            }
#pragma unroll
            for (int o = 1; o < 16; o <<= 1)
                sum += __shfl_xor_sync(0xffffffffu, sum, o);
            float r = __expf(mrow[i] - mn);
            mrow[i] = mn;
            lrow[i] = lrow[i] * r + sum;
#pragma unroll
            for (int j = 0; j < 8; j++) acc[i][j] *= r;
        }
        __syncthreads();

#pragma unroll 2
        for (int k = 0; k < 64; k++) {
            float pv[4], vv[8];
#pragma unroll
            for (int i = 0; i < 4; i++) pv[i] = sP[(ty * 4 + i) * SMP + k];
#pragma unroll
            for (int j = 0; j < 8; j++) vv[j] = sV[k * SMV + j * 16 + tx];
#pragma unroll
            for (int i = 0; i < 4; i++)
#pragma unroll
                for (int j = 0; j < 8; j++) acc[i][j] += pv[i] * vv[j];
        }
    }

#pragma unroll
    for (int i = 0; i < 4; i++) {
        float inv = 1.0f / lrow[i];
        float* op = g_O + ((size_t)b * N_ + q0 + ty * 4 + i) * D_ + h * DH_;
#pragma unroll
        for (int j = 0; j < 8; j++) op[j * 16 + tx] = acc[i][j] * inv;
    }
}

// ---------------- launch -----------------------------------------------------
extern "C" void kernel_launch(void* const* d_in, const int* in_sizes, int n_in,
                              void* d_out, int out_size)
{
    const float* x    = (const float*)d_in[0];
    const float* c    = (const float*)d_in[1];
    const float* wqkv = (const float*)d_in[2];
    const float* wcq  = (const float*)d_in[3];
    const float* wo   = (const float*)d_in[4];
    const float* bo   = (const float*)d_in[5];
    const float* sc   = (const float*)d_in[6];
    const float* csc  = (const float*)d_in[7];
    float* out = (float*)d_out;

    cudaFuncSetAttribute(gemm_mma<0>, cudaFuncAttributeMaxDynamicSharedMemorySize, GEMM_SMEM);
    cudaFuncSetAttribute(gemm_mma<1>, cudaFuncAttributeMaxDynamicSharedMemorySize, GEMM_SMEM);
    cudaFuncSetAttribute(gemm_mma<2>, cudaFuncAttributeMaxDynamicSharedMemorySize, GEMM_SMEM);
    cudaFuncSetAttribute(attn_k, cudaFuncAttributeMaxDynamicSharedMemorySize, ATTN_SMEM);

    // self + cross QKV projections (scatter into (b,h,l,dh) with concat offset)
    gemm_mma<0><<<dim3(D3_ / 128, (B_ * N_) / 128), 256, GEMM_SMEM>>>(x, wqkv, nullptr, nullptr);
    gemm_mma<1><<<dim3(D3_ / 128, (B_ * NC_) / 128), 256, GEMM_SMEM>>>(c, wcq, nullptr, nullptr);

    // L2-norm + scale + RoPE on Q/K
    normrope_k<<<dim3(L_, H_, B_), 128>>>(sc, csc);

    // attention (fp32 SIMT, flash-style)
    attn_k<<<dim3(N_ / 64, H_, B_), 256, ATTN_SMEM>>>();

    // output projection + bias
    gemm_mma<2><<<dim3(D_ / 128, (B_ * N_) / 128), 256, GEMM_SMEM>>>(nullptr, wo, bo, out);
}

// round 4
// speedup vs baseline: 3.9511x; 3.2738x over previous
#include <cuda_runtime.h>
#include <cstdint>
#include <math.h>

#define B_  2
#define N_  2048
#define NC_ 128
#define D_  2048
#define H_  16
#define DH_ 128
#define L_  (N_ + NC_)     // 2176
#define D3_ (3 * D_)       // 6144

// ---------------- scratch (device globals; no allocations allowed) ----------
__device__ float g_Q[(size_t)B_ * H_ * L_ * DH_];   // (b,h,l,dh)
__device__ float g_K[(size_t)B_ * H_ * L_ * DH_];
__device__ float g_V[(size_t)B_ * H_ * L_ * DH_];
__device__ float g_O[(size_t)B_ * N_ * D_];         // (b,n,d) attention output
__device__ float2 g_rope[(size_t)L_ * 64];          // cos/sin table

__device__ __forceinline__ float to_tf32(float x) {
    float r; asm("cvt.rna.tf32.f32 %0, %1;" : "=f"(r) : "f"(x)); return r;
}
__device__ __forceinline__ uint32_t to_tf32_u(float x) {
    float r; asm("cvt.rna.tf32.f32 %0, %1;" : "=f"(r) : "f"(x)); return __float_as_uint(r);
}

// mma.sync m16n8k8 tf32: D += A*B  (row.col)
__device__ __forceinline__ void mma_tf32(float* d, const uint32_t* a, const uint32_t* b) {
    asm volatile(
        "mma.sync.aligned.m16n8k8.row.col.f32.tf32.tf32.f32 "
        "{%0,%1,%2,%3},{%4,%5,%6,%7},{%8,%9},{%0,%1,%2,%3};"
        : "+f"(d[0]), "+f"(d[1]), "+f"(d[2]), "+f"(d[3])
        : "r"(a[0]), "r"(a[1]), "r"(a[2]), "r"(a[3]), "r"(b[0]), "r"(b[1]));
}

__device__ __forceinline__ void cp16(uint32_t saddr, const void* gaddr) {
    asm volatile("cp.async.cg.shared.global [%0], [%1], 16;" :: "r"(saddr), "l"(gaddr));
}
__device__ __forceinline__ uint32_t smem_u32(const void* p) {
    uint32_t a;
    asm("{ .reg .u64 t; cvta.to.shared.u64 t, %1; cvt.u32.u64 %0, t; }" : "=r"(a) : "l"(p));
    return a;
}
#define CP_COMMIT() asm volatile("cp.async.commit_group;" ::: "memory")
#define CP_WAIT1()  asm volatile("cp.async.wait_group 1;" ::: "memory")

// ================= tf32 mma GEMM (cp.async 3-stage) =========================
// C[m][n] = sum_k A[m][k] * W[n][k]; 128x128 CTA tile, KSLAB=16, m-major smem.
// MODE 0: A=x, scatter into g_Q/g_K/g_V at l=n      (rows = b*N_+n)
// MODE 1: A=c, scatter into g_Q/g_K/g_V at l=N_+n   (rows = b*NC_+n)
// MODE 2: A=g_O, out[m][n] = acc + bias[n]
#define KSLAB  16
#define APAD   20                         // floats per smem row (16 + 4 pad)
#define STG_F  (128 * APAD)               // floats per matrix per stage (2560)
#define GEMM_SMEM (3 * 2 * STG_F * 4)     // 61440 bytes

template <int MODE>
__global__ __launch_bounds__(256, 2)
void gemm_mma(const float* __restrict__ A, const float* __restrict__ W,
              const float* __restrict__ bias, float* __restrict__ out)
{
    constexpr int K = D_;
    constexpr int NS = K / KSLAB;         // 128 slabs
    extern __shared__ float sm[];

    const int t = threadIdx.x;
    const int wid = t >> 5, lane = t & 31;
    const int g = lane >> 2, tig = lane & 3;
    const int wm = (wid >> 2) * 64;       // warp m offset (0/64)
    const int wn = (wid & 3) * 32;        // warp n offset
    const int n0 = blockIdx.x * 128;
    const int m0 = blockIdx.y * 128;

    const float* Ag = (MODE == 2) ? g_O : A;

    // cp.async task mapping: thread t handles tasks 2t, 2t+1; row=task>>2, chunk=task&3
    const int r0t = (2 * t) >> 2, c0t = (2 * t) & 3;
    const int r1t = (2 * t + 1) >> 2, c1t = (2 * t + 1) & 3;
    const float* aRow0 = Ag + (size_t)(m0 + r0t) * K + c0t * 4;
    const float* aRow1 = Ag + (size_t)(m0 + r1t) * K + c1t * 4;
    const float* bRow0 = W + (size_t)(n0 + r0t) * K + c0t * 4;
    const float* bRow1 = W + (size_t)(n0 + r1t) * K + c1t * 4;
    const uint32_t sbase = smem_u32(sm);

    float acc[4][4][4];
#pragma unroll
    for (int mi = 0; mi < 4; mi++)
#pragma unroll
        for (int ni = 0; ni < 4; ni++)
#pragma unroll
            for (int r = 0; r < 4; r++) acc[mi][ni][r] = 0.0f;

    // issue loads for a slab into stage s
    auto issue = [&](int slab) {
        const int s = slab % 3;
        const uint32_t as = sbase + (uint32_t)(s * 2 * STG_F) * 4;
        const uint32_t bs = as + (uint32_t)STG_F * 4;
        const int ko = slab * KSLAB;
        cp16(as + (uint32_t)(r0t * APAD + c0t * 4) * 4, aRow0 + ko);
        cp16(as + (uint32_t)(r1t * APAD + c1t * 4) * 4, aRow1 + ko);
        cp16(bs + (uint32_t)(r0t * APAD + c0t * 4) * 4, bRow0 + ko);
        cp16(bs + (uint32_t)(r1t * APAD + c1t * 4) * 4, bRow1 + ko);
    };

    issue(0); CP_COMMIT();
    issue(1); CP_COMMIT();

    for (int kt = 0; kt < NS; kt++) {
        CP_WAIT1();
        __syncthreads();
        if (kt + 2 < NS) issue(kt + 2);
        CP_COMMIT();

        const int s = kt % 3;
        const float* as = sm + s * 2 * STG_F;
        const float* bs = as + STG_F;
#pragma unroll
        for (int ks = 0; ks < 2; ks++) {
            const int k = ks * 8;
            uint32_t bf[4][2];
#pragma unroll
            for (int ni = 0; ni < 4; ni++) {
                const int n = wn + ni * 8 + g;
                bf[ni][0] = to_tf32_u(bs[n * APAD + k + tig]);
                bf[ni][1] = to_tf32_u(bs[n * APAD + k + tig + 4]);
            }
#pragma unroll
            for (int mi = 0; mi < 4; mi++) {
                const int m = wm + mi * 16 + g;
                uint32_t af[4];
                af[0] = to_tf32_u(as[m * APAD + k + tig]);
                af[1] = to_tf32_u(as[(m + 8) * APAD + k + tig]);
                af[2] = to_tf32_u(as[m * APAD + k + tig + 4]);
                af[3] = to_tf32_u(as[(m + 8) * APAD + k + tig + 4]);
#pragma unroll
                for (int ni = 0; ni < 4; ni++)
                    mma_tf32(acc[mi][ni], af, bf[ni]);
            }
        }
    }

    // -------- epilogue: c0/c1 at (row g, cols 2tig,2tig+1), c2/c3 at row g+8
    if (MODE == 0 || MODE == 1) {
        const int part = n0 >> 11;            // 0=q 1=k 2=v
        const int hh   = (n0 & 2047) >> 7;    // head
        float* dst = (part == 0) ? g_Q : (part == 1) ? g_K : g_V;
#pragma unroll
        for (int mi = 0; mi < 4; mi++) {
#pragma unroll
            for (int hi = 0; hi < 2; hi++) {
                const int m = m0 + wm + mi * 16 + g + hi * 8;
                int b, l;
                if (MODE == 0) { b = m >> 11; l = m & 2047; }
                else           { b = m >> 7;  l = N_ + (m & 127); }
                float* rowp = dst + ((size_t)(b * H_ + hh) * L_ + l) * DH_;
#pragma unroll
                for (int ni = 0; ni < 4; ni++) {
                    const int dh = wn + ni * 8 + 2 * tig;
                    float v0 = acc[mi][ni][hi * 2], v1 = acc[mi][ni][hi * 2 + 1];
                    if (part == 2) { v0 = to_tf32(v0); v1 = to_tf32(v1); }  // V consumed by tf32 mma
                    *(float2*)(rowp + dh) = make_float2(v0, v1);
                }
            }
        }
    } else {
#pragma unroll
        for (int mi = 0; mi < 4; mi++) {
#pragma unroll
            for (int hi = 0; hi < 2; hi++) {
                const int m = m0 + wm + mi * 16 + g + hi * 8;
                float* op = out + (size_t)m * D_;
#pragma unroll
                for (int ni = 0; ni < 4; ni++) {
                    const int n = n0 + wn + ni * 8 + 2 * tig;
                    *(float2*)(op + n) = make_float2(acc[mi][ni][hi * 2] + bias[n],
                                                     acc[mi][ni][hi * 2 + 1] + bias[n + 1]);
                }
            }
        }
    }
}

// ---------------- RoPE table (fp64 trig hoisted out of normrope) -------------
__global__ void rope_table_k()
{
    const int l = blockIdx.x, i = threadIdx.x;   // i in [0,64)
    const float invf = (float)(1.0 / pow(10000.0, (double)i / 64.0));
    const float ang  = (float)l * invf;
    g_rope[l * 64 + i] = make_float2((float)cos((double)ang), (float)sin((double)ang));
}

// ---------------- L2-norm + learned scale + RoPE on Q and K -----------------
// Q additionally folded with 1/sqrt(dh); both stored tf32-rounded.
__global__ __launch_bounds__(128)
void normrope_k(const float* __restrict__ scale, const float* __restrict__ cscale)
{
    const int l = blockIdx.x, h = blockIdx.y, b = blockIdx.z;
    const int tid = threadIdx.x;
    __shared__ float buf[128];
    __shared__ float red[4];

    const size_t rbase = ((size_t)(b * H_ + h) * L_ + l) * DH_;
    const float* scp = (l < N_) ? scale : cscale;
    const float scbase = scp[h * DH_ + tid] * 45.25483399593904f;  // sqrt(2048)
    const float smscale = 0.08838834764831845f;                    // 1/sqrt(128)

    const float2 rp = g_rope[l * 64 + (tid & 63)];
    const float cs = rp.x, sn = rp.y;

#pragma unroll
    for (int which = 0; which < 2; which++) {
        float* ptr = ((which == 0) ? g_Q : g_K) + rbase;
        const float sc = (which == 0) ? scbase * smscale : scbase;
        float v = ptr[tid];
        float ss = v * v;
#pragma unroll
        for (int o = 16; o > 0; o >>= 1) ss += __shfl_xor_sync(0xffffffffu, ss, o);
        if ((tid & 31) == 0) red[tid >> 5] = ss;
        __syncthreads();
        float tot = red[0] + red[1] + red[2] + red[3];
        float inv = 1.0f / fmaxf(sqrtf(tot), 1e-12f);
        buf[tid] = v * inv * sc;
        __syncthreads();
        float o;
        if (tid < 64) { float x1 = buf[tid],      x2 = buf[tid + 64]; o = x1 * cs - x2 * sn; }
        else          { float x1 = buf[tid - 64], x2 = buf[tid];      o = x1 * sn + x2 * cs; }
        ptr[tid] = to_tf32(o);
        __syncthreads();
    }
}

// ---------------- flash attention via mma.sync tf32 --------------------------
// CTA: 128 queries (8 warps x 16 rows), key tiles of 64, dh=128.
// Q fragments register-resident; S = Q K^T mma; register online softmax;
// P through per-warp smem; PV mma.
#define SKV 132
#define SVV 136
#define SPD 68
#define ATT_SMEM ((64 * SKV + 64 * SVV + 8 * 16 * SPD) * 4)   // 103424 B

__global__ __launch_bounds__(256, 1)
void attn_mma()
{
    extern __shared__ float sm[];
    float* sK = sm;                        // [64][132] (also Q staging [128][132])
    float* sV = sm + 64 * SKV;             // [64][136]
    float* sP = sm + 64 * SKV + 64 * SVV;  // per-warp [16][68]

    const int qt = blockIdx.x, h = blockIdx.y, b = blockIdx.z;
    const int t = threadIdx.x;
    const int wid = t >> 5, lane = t & 31;
    const int g = lane >> 2, tig = lane & 3;
    const int q0 = qt * 128, wrow = wid * 16;
    const size_t base = (size_t)(b * H_ + h) * L_ * DH_;

    // ---- stage Q tile into smem (reuse sK..sV region), then load fragments
    {
        const float* gq = g_Q + base + (size_t)q0 * DH_;
#pragma unroll
        for (int ii = 0; ii < 16; ii++) {
            int idx = ii * 256 + t;
            int r = idx >> 5, c4 = (idx & 31) * 4;
            float4 v = *(const float4*)(gq + (size_t)r * DH_ + c4);
            *(float4*)(sm + r * SKV + c4) = v;
        }
    }
    __syncthreads();
    uint32_t qf[16][4];
#pragma unroll
    for (int ks = 0; ks < 16; ks++) {
        qf[ks][0] = __float_as_uint(sm[(wrow + g) * SKV + ks * 8 + tig]);
        qf[ks][1] = __float_as_uint(sm[(wrow + g + 8) * SKV + ks * 8 + tig]);
        qf[ks][2] = __float_as_uint(sm[(wrow + g) * SKV + ks * 8 + tig + 4]);
        qf[ks][3] = __float_as_uint(sm[(wrow + g + 8) * SKV + ks * 8 + tig + 4]);
    }

    float acc[16][4];
#pragma unroll
    for (int nt = 0; nt < 16; nt++)
#pragma unroll
        for (int r = 0; r < 4; r++) acc[nt][r] = 0.0f;
    float m0 = -INFINITY, m1 = -INFINITY, l0 = 0.0f, l1 = 0.0f;

    float* Pw = sP + wid * (16 * SPD);
    const float* gk = g_K + base;
    const float* gv = g_V + base;

    for (int kt = 0; kt < L_ / 64; kt++) {
        const int k0 = kt * 64;
        __syncthreads();
#pragma unroll
        for (int ii = 0; ii < 8; ii++) {
            int idx = ii * 256 + t;
            int r = idx >> 5, c4 = (idx & 31) * 4;
            float4 kv = *(const float4*)(gk + (size_t)(k0 + r) * DH_ + c4);
            *(float4*)(sK + r * SKV + c4) = kv;
            float4 vv = *(const float4*)(gv + (size_t)(k0 + r) * DH_ + c4);
            *(float4*)(sV + r * SVV + c4) = vv;
        }
        __syncthreads();

        // ---- S = Q K^T  (warp rows x 64 keys)
        float sfr[8][4];
#pragma unroll
        for (int nt = 0; nt < 8; nt++)
#pragma unroll
            for (int r = 0; r < 4; r++) sfr[nt][r] = 0.0f;
#pragma unroll
        for (int ks = 0; ks < 16; ks++) {
            const int kk = ks * 8;
#pragma unroll
            for (int nt = 0; nt < 8; nt++) {
                uint32_t kf[2];
                kf[0] = __float_as_uint(sK[(nt * 8 + g) * SKV + kk + tig]);
                kf[1] = __float_as_uint(sK[(nt * 8 + g) * SKV + kk + tig + 4]);
                mma_tf32(sfr[nt], qf[ks], kf);
            }
        }

        // ---- online softmax (rows g and g+8)
        float mx0 = -INFINITY, mx1 = -INFINITY;
#pragma unroll
        for (int nt = 0; nt < 8; nt++) {
            mx0 = fmaxf(mx0, fmaxf(sfr[nt][0], sfr[nt][1]));
            mx1 = fmaxf(mx1, fmaxf(sfr[nt][2], sfr[nt][3]));
        }
        mx0 = fmaxf(mx0, __shfl_xor_sync(0xffffffffu, mx0, 1));
        mx0 = fmaxf(mx0, __shfl_xor_sync(0xffffffffu, mx0, 2));
        mx1 = fmaxf(mx1, __shfl_xor_sync(0xffffffffu, mx1, 1));
        mx1 = fmaxf(mx1, __shfl_xor_sync(0xffffffffu, mx1, 2));
        const float mn0 = fmaxf(m0, mx0), mn1 = fmaxf(m1, mx1);
        const float r0 = __expf(m0 - mn0), r1 = __expf(m1 - mn1);
        m0 = mn0; m1 = mn1;
        float s0 = 0.0f, s1 = 0.0f;
#pragma unroll
        for (int nt = 0; nt < 8; nt++) {
            float p00 = __expf(sfr[nt][0] - mn0);
            float p01 = __expf(sfr[nt][1] - mn0);
            float p10 = __expf(sfr[nt][2] - mn1);
            float p11 = __expf(sfr[nt][3] - mn1);
            s0 += p00 + p01; s1 += p10 + p11;
            *(float2*)(Pw + g * SPD + nt * 8 + 2 * tig) = make_float2(to_tf32(p00), to_tf32(p01));
            *(float2*)(Pw + (g + 8) * SPD + nt * 8 + 2 * tig) = make_float2(to_tf32(p10), to_tf32(p11));
        }
        s0 += __shfl_xor_sync(0xffffffffu, s0, 1);
        s0 += __shfl_xor_sync(0xffffffffu, s0, 2);
        s1 += __shfl_xor_sync(0xffffffffu, s1, 1);
        s1 += __shfl_xor_sync(0xffffffffu, s1, 2);
        l0 = l0 * r0 + s0;
        l1 = l1 * r1 + s1;
#pragma unroll
        for (int nt = 0; nt < 16; nt++) {
            acc[nt][0] *= r0; acc[nt][1] *= r0;
            acc[nt][2] *= r1; acc[nt][3] *= r1;
        }
        __syncwarp();

        // ---- PV: acc += P V
#pragma unroll
        for (int ks = 0; ks < 8; ks++) {
            const int kk = ks * 8;
            uint32_t pf[4];
            pf[0] = __float_as_uint(Pw[g * SPD + kk + tig]);
            pf[1] = __float_as_uint(Pw[(g + 8) * SPD + kk + tig]);
            pf[2] = __float_as_uint(Pw[g * SPD + kk + tig + 4]);
            pf[3] = __float_as_uint(Pw[(g + 8) * SPD + kk + tig + 4]);
#pragma unroll
            for (int nt = 0; nt < 16; nt++) {
                uint32_t vf[2];
                vf[0] = __float_as_uint(sV[(kk + tig) * SVV + nt * 8 + g]);
                vf[1] = __float_as_uint(sV[(kk + tig + 4) * SVV + nt * 8 + g]);
                mma_tf32(acc[nt], pf, vf);
            }
        }
        __syncwarp();
    }

    // ---- epilogue
    const float i0 = 1.0f / l0, i1 = 1.0f / l1;
    float* o0 = g_O + ((size_t)b * N_ + q0 + wrow + g) * D_ + h * DH_;
    float* o1 = g_O + ((size_t)b * N_ + q0 + wrow + g + 8) * D_ + h * DH_;
#pragma unroll
    for (int nt = 0; nt < 16; nt++) {
        const int col = nt * 8 + 2 * tig;
        *(float2*)(o0 + col) = make_float2(acc[nt][0] * i0, acc[nt][1] * i0);
        *(float2*)(o1 + col) = make_float2(acc[nt][2] * i1, acc[nt][3] * i1);
    }
}

// ---------------- launch -----------------------------------------------------
extern "C" void kernel_launch(void* const* d_in, const int* in_sizes, int n_in,
                              void* d_out, int out_size)
{
    const float* x    = (const float*)d_in[0];
    const float* c    = (const float*)d_in[1];
    const float* wqkv = (const float*)d_in[2];
    const float* wcq  = (const float*)d_in[3];
    const float* wo   = (const float*)d_in[4];
    const float* bo   = (const float*)d_in[5];
    const float* sc   = (const float*)d_in[6];
    const float* csc  = (const float*)d_in[7];
    float* out = (float*)d_out;

    cudaFuncSetAttribute(gemm_mma<0>, cudaFuncAttributeMaxDynamicSharedMemorySize, GEMM_SMEM);
    cudaFuncSetAttribute(gemm_mma<1>, cudaFuncAttributeMaxDynamicSharedMemorySize, GEMM_SMEM);
    cudaFuncSetAttribute(gemm_mma<2>, cudaFuncAttributeMaxDynamicSharedMemorySize, GEMM_SMEM);
    cudaFuncSetAttribute(attn_mma, cudaFuncAttributeMaxDynamicSharedMemorySize, ATT_SMEM);

    rope_table_k<<<L_, 64>>>();

    gemm_mma<0><<<dim3(D3_ / 128, (B_ * N_) / 128), 256, GEMM_SMEM>>>(x, wqkv, nullptr, nullptr);
    gemm_mma<1><<<dim3(D3_ / 128, (B_ * NC_) / 128), 256, GEMM_SMEM>>>(c, wcq, nullptr, nullptr);

    normrope_k<<<dim3(L_, H_, B_), 128>>>(sc, csc);

    attn_mma<<<dim3(N_ / 128, H_, B_), 256, ATT_SMEM>>>();

    gemm_mma<2><<<dim3(D_ / 128, (B_ * N_) / 128), 256, GEMM_SMEM>>>(nullptr, wo, bo, out);
}

// round 5
// speedup vs baseline: 7.0527x; 1.7850x over previous
#include <cuda_runtime.h>
#include <cuda_fp16.h>
#include <cstdint>
#include <math.h>

#define B_  2
#define N_  2048
#define NC_ 128
#define D_  2048
#define H_  16
#define DH_ 128
#define L_  (N_ + NC_)     // 2176
#define D3_ (3 * D_)       // 6144

// ---------------- scratch (device globals; no allocations allowed) ----------
__device__ float  g_Q[(size_t)B_ * H_ * L_ * DH_];    // fp32 (b,h,l,dh) pre-norm
__device__ float  g_K[(size_t)B_ * H_ * L_ * DH_];
__device__ __half g_Qh[(size_t)B_ * H_ * L_ * DH_];   // fp16 post-norm/rope
__device__ __half g_Kh[(size_t)B_ * H_ * L_ * DH_];
__device__ __half g_Vt[(size_t)B_ * H_ * DH_ * L_];   // fp16 (b,h,dh,l) transposed
__device__ __half g_Oh[(size_t)B_ * N_ * D_];         // fp16 attention output
__device__ __half g_hx[(size_t)B_ * N_ * D_];
__device__ __half g_hc[(size_t)B_ * NC_ * D_];
__device__ __half g_hwqkv[(size_t)D3_ * D_];
__device__ __half g_hwcq[(size_t)D3_ * D_];
__device__ __half g_hwo[(size_t)D_ * D_];
__device__ float2 g_rope[(size_t)L_ * 64];            // cos/sin table

__device__ __forceinline__ uint32_t smem_u32(const void* p) {
    uint32_t a;
    asm("{ .reg .u64 t; cvta.to.shared.u64 t, %1; cvt.u32.u64 %0, t; }" : "=r"(a) : "l"(p));
    return a;
}
__device__ __forceinline__ void cp16(uint32_t saddr, const void* gaddr) {
    asm volatile("cp.async.cg.shared.global [%0], [%1], 16;" :: "r"(saddr), "l"(gaddr));
}
#define CP_COMMIT() asm volatile("cp.async.commit_group;" ::: "memory")
#define CP_WAIT1()  asm volatile("cp.async.wait_group 1;" ::: "memory")

// mma.sync m16n8k16 fp16 inputs, fp32 accum (row.col)
__device__ __forceinline__ void mma_f16(float* d, const uint32_t* a, const uint32_t* b) {
    asm volatile(
        "mma.sync.aligned.m16n8k16.row.col.f32.f16.f16.f32 "
        "{%0,%1,%2,%3},{%4,%5,%6,%7},{%8,%9},{%0,%1,%2,%3};"
        : "+f"(d[0]), "+f"(d[1]), "+f"(d[2]), "+f"(d[3])
        : "r"(a[0]), "r"(a[1]), "r"(a[2]), "r"(a[3]), "r"(b[0]), "r"(b[1]));
}
__device__ __forceinline__ uint32_t ld32h(const __half* p) { return *(const uint32_t*)p; }

// ---------------- fp32 -> fp16 conversion prepass ---------------------------
__global__ void cvt_h(const float* __restrict__ src, __half* __restrict__ dst, int n8)
{
    for (int i = blockIdx.x * blockDim.x + threadIdx.x; i < n8; i += gridDim.x * blockDim.x) {
        float4 a = *(const float4*)(src + i * 8);
        float4 b = *(const float4*)(src + i * 8 + 4);
        __half2 h0 = __floats2half2_rn(a.x, a.y);
        __half2 h1 = __floats2half2_rn(a.z, a.w);
        __half2 h2 = __floats2half2_rn(b.x, b.y);
        __half2 h3 = __floats2half2_rn(b.z, b.w);
        uint4 o;
        o.x = *(uint32_t*)&h0; o.y = *(uint32_t*)&h1;
        o.z = *(uint32_t*)&h2; o.w = *(uint32_t*)&h3;
        *(uint4*)(dst + i * 8) = o;
    }
}

// ================= fp16 mma GEMM (cp.async 3-stage) =========================
// C[m][n] = sum_k A[m][k] * W[n][k]; 128x128 CTA tile, KSLAB=32 halves/slab.
// MODE 0: A=hx, scatter: Q/K fp32 into g_Q/g_K; V fp16 into g_Vt (transposed)
// MODE 1: A=hc, same with l = N_+n
// MODE 2: A=g_Oh, out[m][n] = acc + bias[n]  (fp32 out)
#define KSLAB  32
#define APADH  40                          // halves per smem row
#define STG_H  (128 * APADH)               // halves per matrix per stage (5120)
#define GEMM_SMEM (3 * 2 * STG_H * 2)      // 61440 bytes

template <int MODE>
__global__ __launch_bounds__(256, 2)
void gemm_h(const __half* __restrict__ A, const __half* __restrict__ W,
            const float* __restrict__ bias, float* __restrict__ out)
{
    constexpr int K = D_;
    constexpr int NS = K / KSLAB;          // 64 slabs
    extern __shared__ __half smh[];

    const int t = threadIdx.x;
    const int wid = t >> 5, lane = t & 31;
    const int g = lane >> 2, tig = lane & 3;
    const int wm = (wid >> 2) * 64;        // warp m offset (0/64)
    const int wn = (wid & 3) * 32;         // warp n offset
    const int n0 = blockIdx.x * 128;
    const int m0 = blockIdx.y * 128;

    // cp.async mapping: 512 tasks/matrix (128 rows x 4 chunks of 8 halves)
    const int rT = t >> 1;                 // row
    const int cT = (t & 1) * 2;            // first chunk (covers cT, cT+1)
    const __half* aRow = A + (size_t)(m0 + rT) * K + cT * 8;
    const __half* bRow = W + (size_t)(n0 + rT) * K + cT * 8;
    const uint32_t sbase = smem_u32(smh);

    float acc[4][4][4];
#pragma unroll
    for (int mi = 0; mi < 4; mi++)
#pragma unroll
        for (int ni = 0; ni < 4; ni++)
#pragma unroll
            for (int r = 0; r < 4; r++) acc[mi][ni][r] = 0.0f;

    auto issue = [&](int slab) {
        const int s = slab % 3;
        const uint32_t as = sbase + (uint32_t)(s * 2 * STG_H) * 2;
        const uint32_t bs = as + (uint32_t)STG_H * 2;
        const int ko = slab * KSLAB;
        const uint32_t soff = (uint32_t)(rT * APADH + cT * 8) * 2;
        cp16(as + soff,      aRow + ko);
        cp16(as + soff + 16, aRow + ko + 8);
        cp16(bs + soff,      bRow + ko);
        cp16(bs + soff + 16, bRow + ko + 8);
    };

    issue(0); CP_COMMIT();
    issue(1); CP_COMMIT();

    for (int kt = 0; kt < NS; kt++) {
        CP_WAIT1();
        __syncthreads();
        if (kt + 2 < NS) issue(kt + 2);
        CP_COMMIT();

        const __half* as = smh + (kt % 3) * 2 * STG_H;
        const __half* bs = as + STG_H;
#pragma unroll
        for (int ks = 0; ks < 2; ks++) {
            const int kb = ks * 16 + 2 * tig;
            uint32_t bf[4][2];
#pragma unroll
            for (int ni = 0; ni < 4; ni++) {
                const int n = wn + ni * 8 + g;
                bf[ni][0] = ld32h(bs + n * APADH + kb);
                bf[ni][1] = ld32h(bs + n * APADH + kb + 8);
            }
#pragma unroll
            for (int mi = 0; mi < 4; mi++) {
                const int m = wm + mi * 16 + g;
                uint32_t af[4];
                af[0] = ld32h(as + m * APADH + kb);
                af[1] = ld32h(as + (m + 8) * APADH + kb);
                af[2] = ld32h(as + m * APADH + kb + 8);
                af[3] = ld32h(as + (m + 8) * APADH + kb + 8);
#pragma unroll
                for (int ni = 0; ni < 4; ni++)
                    mma_f16(acc[mi][ni], af, bf[ni]);
            }
        }
    }

    // -------- epilogue
    if (MODE == 0 || MODE == 1) {
        const int part = n0 >> 11;            // 0=q 1=k 2=v
        const int hh   = (n0 & 2047) >> 7;    // head
#pragma unroll
        for (int mi = 0; mi < 4; mi++) {
#pragma unroll
            for (int hi = 0; hi < 2; hi++) {
                const int m = m0 + wm + mi * 16 + g + hi * 8;
                int b, l;
                if (MODE == 0) { b = m >> 11; l = m & 2047; }
                else           { b = m >> 7;  l = N_ + (m & 127); }
                if (part < 2) {
                    float* dst = (part == 0) ? g_Q : g_K;
                    float* rowp = dst + ((size_t)(b * H_ + hh) * L_ + l) * DH_;
#pragma unroll
                    for (int ni = 0; ni < 4; ni++) {
                        const int dh = wn + ni * 8 + 2 * tig;
                        *(float2*)(rowp + dh) = make_float2(acc[mi][ni][hi * 2], acc[mi][ni][hi * 2 + 1]);
                    }
                } else {
                    __half* vb = g_Vt + (size_t)(b * H_ + hh) * DH_ * L_;
#pragma unroll
                    for (int ni = 0; ni < 4; ni++) {
                        const int dh = wn + ni * 8 + 2 * tig;
                        vb[(size_t)dh * L_ + l]       = __float2half(acc[mi][ni][hi * 2]);
                        vb[(size_t)(dh + 1) * L_ + l] = __float2half(acc[mi][ni][hi * 2 + 1]);
                    }
                }
            }
        }
    } else {
#pragma unroll
        for (int mi = 0; mi < 4; mi++) {
#pragma unroll
            for (int hi = 0; hi < 2; hi++) {
                const int m = m0 + wm + mi * 16 + g + hi * 8;
                float* op = out + (size_t)m * D_;
#pragma unroll
                for (int ni = 0; ni < 4; ni++) {
                    const int n = n0 + wn + ni * 8 + 2 * tig;
                    *(float2*)(op + n) = make_float2(acc[mi][ni][hi * 2] + bias[n],
                                                     acc[mi][ni][hi * 2 + 1] + bias[n + 1]);
                }
            }
        }
    }
}

// ---------------- RoPE table (fp64 trig, tiny) -------------------------------
__global__ void rope_table_k()
{
    const int l = blockIdx.x, i = threadIdx.x;   // i in [0,64)
    const float invf = (float)(1.0 / pow(10000.0, (double)i / 64.0));
    const float ang  = (float)l * invf;
    g_rope[l * 64 + i] = make_float2((float)cos((double)ang), (float)sin((double)ang));
}

// ---------------- L2-norm + scale + RoPE; fp32 in, fp16 out ------------------
__global__ __launch_bounds__(128)
void normrope_k(const float* __restrict__ scale, const float* __restrict__ cscale)
{
    const int l = blockIdx.x, h = blockIdx.y, b = blockIdx.z;
    const int tid = threadIdx.x;
    __shared__ float buf[128];
    __shared__ float red[4];

    const size_t rbase = ((size_t)(b * H_ + h) * L_ + l) * DH_;
    const float* scp = (l < N_) ? scale : cscale;
    const float scbase = scp[h * DH_ + tid] * 45.25483399593904f;  // sqrt(2048)
    const float smscale = 0.08838834764831845f;                    // 1/sqrt(128)

    const float2 rp = g_rope[l * 64 + (tid & 63)];
    const float cs = rp.x, sn = rp.y;

#pragma unroll
    for (int which = 0; which < 2; which++) {
        const float* ptr = ((which == 0) ? g_Q : g_K) + rbase;
        __half* hout = ((which == 0) ? g_Qh : g_Kh) + rbase;
        const float sc = (which == 0) ? scbase * smscale : scbase;
        float v = ptr[tid];
        float ss = v * v;
#pragma unroll
        for (int o = 16; o > 0; o >>= 1) ss += __shfl_xor_sync(0xffffffffu, ss, o);
        if ((tid & 31) == 0) red[tid >> 5] = ss;
        __syncthreads();
        float tot = red[0] + red[1] + red[2] + red[3];
        float inv = 1.0f / fmaxf(sqrtf(tot), 1e-12f);
        buf[tid] = v * inv * sc;
        __syncthreads();
        float o;
        if (tid < 64) { float x1 = buf[tid],      x2 = buf[tid + 64]; o = x1 * cs - x2 * sn; }
        else          { float x1 = buf[tid - 64], x2 = buf[tid];      o = x1 * sn + x2 * cs; }
        hout[tid] = __float2half(o);
        __syncthreads();
    }
}

// ---------------- flash attention, all-fp16 mma ------------------------------
// CTA: 128 queries (8 warps x 16), key tiles of 64, double-buffered cp.async.
#define SKH  136                         // K smem row stride (halves)
#define SVTH 72                          // Vt smem row stride (halves)
#define SPDH 72                          // P smem row stride (halves)
#define OFF_K   0                        // 2 x 64*136 halves
#define OFF_VT  (2 * 64 * SKH)           // 2 x 128*72 halves
#define OFF_P   (OFF_VT + 2 * 128 * SVTH)
#define ATT_HALVES (OFF_P + 8 * 16 * SPDH)
#define ATT_SMEM (ATT_HALVES * 2)        // 90112 bytes

__global__ __launch_bounds__(256)
void attn_h()
{
    extern __shared__ __half smh[];
    const int qt = blockIdx.x, h = blockIdx.y, b = blockIdx.z;
    const int t = threadIdx.x;
    const int wid = t >> 5, lane = t & 31;
    const int g = lane >> 2, tig = lane & 3;
    const int q0 = qt * 128, wrow = wid * 16;
    const size_t base = (size_t)(b * H_ + h) * L_ * DH_;
    const uint32_t sbase = smem_u32(smh);

    // ---- stage Q tile into (K-buffer region), load fragments
    {
        const __half* gq = g_Qh + base + (size_t)q0 * DH_;
#pragma unroll
        for (int ii = 0; ii < 8; ii++) {
            int idx = ii * 256 + t;
            int r = idx >> 4, c8 = (idx & 15) * 8;
            *(uint4*)(smh + r * SKH + c8) = *(const uint4*)(gq + (size_t)r * DH_ + c8);
        }
    }
    __syncthreads();
    uint32_t qf[8][4];
#pragma unroll
    for (int ks = 0; ks < 8; ks++) {
        const int kb = ks * 16 + 2 * tig;
        qf[ks][0] = ld32h(smh + (wrow + g) * SKH + kb);
        qf[ks][1] = ld32h(smh + (wrow + g + 8) * SKH + kb);
        qf[ks][2] = ld32h(smh + (wrow + g) * SKH + kb + 8);
        qf[ks][3] = ld32h(smh + (wrow + g + 8) * SKH + kb + 8);
    }
    __syncthreads();

    const __half* gk = g_Kh + base;
    const __half* gvt = g_Vt + (size_t)(b * H_ + h) * DH_ * L_;

    // cp.async fill of K and Vt tiles (buffer bb)
    auto issue = [&](int kt) {
        const int bb = kt & 1;
        const int k0 = kt * 64;
        // K: 64 rows x 16 chunks
#pragma unroll
        for (int ii = 0; ii < 4; ii++) {
            int idx = ii * 256 + t;
            int r = idx >> 4, c8 = (idx & 15) * 8;
            cp16(sbase + (uint32_t)(OFF_K + bb * 64 * SKH + r * SKH + c8) * 2,
                 gk + (size_t)(k0 + r) * DH_ + c8);
        }
        // Vt: 128 dh-rows x 8 chunks
#pragma unroll
        for (int ii = 0; ii < 4; ii++) {
            int idx = ii * 256 + t;
            int dh = idx >> 3, c8 = (idx & 7) * 8;
            cp16(sbase + (uint32_t)(OFF_VT + bb * 128 * SVTH + dh * SVTH + c8) * 2,
                 gvt + (size_t)dh * L_ + k0 + c8);
        }
    };

    float acc[16][4];
#pragma unroll
    for (int nt = 0; nt < 16; nt++)
#pragma unroll
        for (int r = 0; r < 4; r++) acc[nt][r] = 0.0f;
    float m0 = -INFINITY, m1 = -INFINITY, l0 = 0.0f, l1 = 0.0f;

    __half* Pw = smh + OFF_P + wid * (16 * SPDH);

    issue(0); CP_COMMIT();

    constexpr int NT = L_ / 64;   // 34
    for (int kt = 0; kt < NT; kt++) {
        __syncthreads();                 // everyone done reading buffer (kt+1)&1
        if (kt + 1 < NT) issue(kt + 1);
        CP_COMMIT();
        CP_WAIT1();                      // tile kt arrived
        __syncthreads();

        const __half* sK = smh + OFF_K + (kt & 1) * 64 * SKH;
        const __half* sVt = smh + OFF_VT + (kt & 1) * 128 * SVTH;

        // ---- S = Q K^T
        float sfr[8][4];
#pragma unroll
        for (int nt = 0; nt < 8; nt++)
#pragma unroll
            for (int r = 0; r < 4; r++) sfr[nt][r] = 0.0f;
#pragma unroll
        for (int ks = 0; ks < 8; ks++) {
            const int kb = ks * 16 + 2 * tig;
#pragma unroll
            for (int nt = 0; nt < 8; nt++) {
                uint32_t kf[2];
                kf[0] = ld32h(sK + (nt * 8 + g) * SKH + kb);
                kf[1] = ld32h(sK + (nt * 8 + g) * SKH + kb + 8);
                mma_f16(sfr[nt], qf[ks], kf);
            }
        }

        // ---- online softmax (rows g and g+8)
        float mx0 = -INFINITY, mx1 = -INFINITY;
#pragma unroll
        for (int nt = 0; nt < 8; nt++) {
            mx0 = fmaxf(mx0, fmaxf(sfr[nt][0], sfr[nt][1]));
            mx1 = fmaxf(mx1, fmaxf(sfr[nt][2], sfr[nt][3]));
        }
        mx0 = fmaxf(mx0, __shfl_xor_sync(0xffffffffu, mx0, 1));
        mx0 = fmaxf(mx0, __shfl_xor_sync(0xffffffffu, mx0, 2));
        mx1 = fmaxf(mx1, __shfl_xor_sync(0xffffffffu, mx1, 1));
        mx1 = fmaxf(mx1, __shfl_xor_sync(0xffffffffu, mx1, 2));
        const float mn0 = fmaxf(m0, mx0), mn1 = fmaxf(m1, mx1);
        const float r0 = __expf(m0 - mn0), r1 = __expf(m1 - mn1);
        m0 = mn0; m1 = mn1;
        float s0 = 0.0f, s1 = 0.0f;
#pragma unroll
        for (int nt = 0; nt < 8; nt++) {
            float p00 = __expf(sfr[nt][0] - mn0);
            float p01 = __expf(sfr[nt][1] - mn0);
            float p10 = __expf(sfr[nt][2] - mn1);
            float p11 = __expf(sfr[nt][3] - mn1);
            s0 += p00 + p01; s1 += p10 + p11;
            __half2 hp0 = __floats2half2_rn(p00, p01);
            __half2 hp1 = __floats2half2_rn(p10, p11);
            *(__half2*)(Pw + g * SPDH + nt * 8 + 2 * tig) = hp0;
            *(__half2*)(Pw + (g + 8) * SPDH + nt * 8 + 2 * tig) = hp1;
        }
        s0 += __shfl_xor_sync(0xffffffffu, s0, 1);
        s0 += __shfl_xor_sync(0xffffffffu, s0, 2);
        s1 += __shfl_xor_sync(0xffffffffu, s1, 1);
        s1 += __shfl_xor_sync(0xffffffffu, s1, 2);
        l0 = l0 * r0 + s0;
        l1 = l1 * r1 + s1;
#pragma unroll
        for (int nt = 0; nt < 16; nt++) {
            acc[nt][0] *= r0; acc[nt][1] *= r0;
            acc[nt][2] *= r1; acc[nt][3] *= r1;
        }
        __syncwarp();

        // ---- PV: acc += P V   (V^T resident: b-frag rows are dh, cols keys)
#pragma unroll
        for (int ks = 0; ks < 4; ks++) {
            const int kb = ks * 16 + 2 * tig;
            uint32_t pf[4];
            pf[0] = ld32h(Pw + g * SPDH + kb);
            pf[1] = ld32h(Pw + (g + 8) * SPDH + kb);
            pf[2] = ld32h(Pw + g * SPDH + kb + 8);
            pf[3] = ld32h(Pw + (g + 8) * SPDH + kb + 8);
#pragma unroll
            for (int nt = 0; nt < 16; nt++) {
                uint32_t vf[2];
                vf[0] = ld32h(sVt + (nt * 8 + g) * SVTH + kb);
                vf[1] = ld32h(sVt + (nt * 8 + g) * SVTH + kb + 8);
                mma_f16(acc[nt], pf, vf);
            }
        }
        __syncwarp();
    }

    // ---- epilogue (fp16 out)
    const float i0 = 1.0f / l0, i1 = 1.0f / l1;
    __half* o0 = g_Oh + ((size_t)b * N_ + q0 + wrow + g) * D_ + h * DH_;
    __half* o1 = g_Oh + ((size_t)b * N_ + q0 + wrow + g + 8) * D_ + h * DH_;
#pragma unroll
    for (int nt = 0; nt < 16; nt++) {
        const int col = nt * 8 + 2 * tig;
        *(__half2*)(o0 + col) = __floats2half2_rn(acc[nt][0] * i0, acc[nt][1] * i0);
        *(__half2*)(o1 + col) = __floats2half2_rn(acc[nt][2] * i1, acc[nt][3] * i1);
    }
}

// ---------------- launch -----------------------------------------------------
extern "C" void kernel_launch(void* const* d_in, const int* in_sizes, int n_in,
                              void* d_out, int out_size)
{
    const float* x    = (const float*)d_in[0];
    const float* c    = (const float*)d_in[1];
    const float* wqkv = (const float*)d_in[2];
    const float* wcq  = (const float*)d_in[3];
    const float* wo   = (const float*)d_in[4];
    const float* bo   = (const float*)d_in[5];
    const float* sc   = (const float*)d_in[6];
    const float* csc  = (const float*)d_in[7];
    float* out = (float*)d_out;

    cudaFuncSetAttribute(gemm_h<0>, cudaFuncAttributeMaxDynamicSharedMemorySize, GEMM_SMEM);
    cudaFuncSetAttribute(gemm_h<1>, cudaFuncAttributeMaxDynamicSharedMemorySize, GEMM_SMEM);
    cudaFuncSetAttribute(gemm_h<2>, cudaFuncAttributeMaxDynamicSharedMemorySize, GEMM_SMEM);
    cudaFuncSetAttribute(attn_h, cudaFuncAttributeMaxDynamicSharedMemorySize, ATT_SMEM);

    __half *hx, *hc, *hwqkv, *hwcq, *hwo;
    cudaGetSymbolAddress((void**)&hx, g_hx);
    cudaGetSymbolAddress((void**)&hc, g_hc);
    cudaGetSymbolAddress((void**)&hwqkv, g_hwqkv);
    cudaGetSymbolAddress((void**)&hwcq, g_hwcq);
    cudaGetSymbolAddress((void**)&hwo, g_hwo);

    rope_table_k<<<L_, 64>>>();
    cvt_h<<<1024, 256>>>(x, hx, (B_ * N_ * D_) / 8);
    cvt_h<<<256, 256>>>(c, hc, (B_ * NC_ * D_) / 8);
    cvt_h<<<1024, 256>>>(wqkv, hwqkv, (D3_ * D_) / 8);
    cvt_h<<<1024, 256>>>(wcq, hwcq, (D3_ * D_) / 8);
    cvt_h<<<1024, 256>>>(wo, hwo, (D_ * D_) / 8);

    gemm_h<0><<<dim3(D3_ / 128, (B_ * N_) / 128), 256, GEMM_SMEM>>>(hx, hwqkv, nullptr, nullptr);
    gemm_h<1><<<dim3(D3_ / 128, (B_ * NC_) / 128), 256, GEMM_SMEM>>>(hc, hwcq, nullptr, nullptr);

    normrope_k<<<dim3(L_, H_, B_), 128>>>(sc, csc);

    attn_h<<<dim3(N_ / 128, H_, B_), 256, ATT_SMEM>>>();

    __half* oh;
    cudaGetSymbolAddress((void**)&oh, g_Oh);
    gemm_h<2><<<dim3(D_ / 128, (B_ * N_) / 128), 256, GEMM_SMEM>>>(oh, hwo, bo, out);
}

// round 6
// speedup vs baseline: 8.4092x; 1.1923x over previous
#include <cuda_runtime.h>
#include <cuda_fp16.h>
#include <cstdint>
#include <math.h>

#define B_  2
#define N_  2048
#define NC_ 128
#define D_  2048
#define H_  16
#define DH_ 128
#define L_  (N_ + NC_)     // 2176
#define D3_ (3 * D_)       // 6144

// ---------------- scratch (device globals; no allocations allowed) ----------
__device__ float  g_Q[(size_t)B_ * H_ * L_ * DH_];    // fp32 (b,h,l,dh) pre-norm
__device__ float  g_K[(size_t)B_ * H_ * L_ * DH_];
__device__ __half g_Qh[(size_t)B_ * H_ * L_ * DH_];   // fp16 post-norm/rope
__device__ __half g_Kh[(size_t)B_ * H_ * L_ * DH_];
__device__ __half g_Vt[(size_t)B_ * H_ * DH_ * L_];   // fp16 (b,h,dh,l) transposed
__device__ __half g_Oh[(size_t)B_ * N_ * D_];         // fp16 attention output
__device__ __half g_hx[(size_t)B_ * N_ * D_];
__device__ __half g_hc[(size_t)B_ * NC_ * D_];
__device__ __half g_hwqkv[(size_t)D3_ * D_];
__device__ __half g_hwcq[(size_t)D3_ * D_];
__device__ __half g_hwo[(size_t)D_ * D_];
__device__ float2 g_rope[(size_t)L_ * 64];            // cos/sin table

__device__ __forceinline__ uint32_t smem_u32(const void* p) {
    uint32_t a;
    asm("{ .reg .u64 t; cvta.to.shared.u64 t, %1; cvt.u32.u64 %0, t; }" : "=r"(a) : "l"(p));
    return a;
}
__device__ __forceinline__ void cp16(uint32_t saddr, const void* gaddr) {
    asm volatile("cp.async.cg.shared.global [%0], [%1], 16;" :: "r"(saddr), "l"(gaddr));
}
#define CP_COMMIT() asm volatile("cp.async.commit_group;" ::: "memory")
#define CP_WAIT1()  asm volatile("cp.async.wait_group 1;" ::: "memory")

// mma.sync m16n8k16 fp16 inputs, fp32 accum (row.col)
__device__ __forceinline__ void mma_f16(float* d, const uint32_t* a, const uint32_t* b) {
    asm volatile(
        "mma.sync.aligned.m16n8k16.row.col.f32.f16.f16.f32 "
        "{%0,%1,%2,%3},{%4,%5,%6,%7},{%8,%9},{%0,%1,%2,%3};"
        : "+f"(d[0]), "+f"(d[1]), "+f"(d[2]), "+f"(d[3])
        : "r"(a[0]), "r"(a[1]), "r"(a[2]), "r"(a[3]), "r"(b[0]), "r"(b[1]));
}
__device__ __forceinline__ void ldmx4(uint32_t* r, uint32_t addr) {
    asm volatile("ldmatrix.sync.aligned.m8n8.x4.shared.b16 {%0,%1,%2,%3}, [%4];"
        : "=r"(r[0]), "=r"(r[1]), "=r"(r[2]), "=r"(r[3]) : "r"(addr));
}
__device__ __forceinline__ uint32_t ld32h(const __half* p) { return *(const uint32_t*)p; }

// ---------------- fp32 -> fp16 conversion prepass ---------------------------
__global__ void cvt_h(const float* __restrict__ src, __half* __restrict__ dst, int n8)
{
    for (int i = blockIdx.x * blockDim.x + threadIdx.x; i < n8; i += gridDim.x * blockDim.x) {
        float4 a = *(const float4*)(src + i * 8);
        float4 b = *(const float4*)(src + i * 8 + 4);
        __half2 h0 = __floats2half2_rn(a.x, a.y);
        __half2 h1 = __floats2half2_rn(a.z, a.w);
        __half2 h2 = __floats2half2_rn(b.x, b.y);
        __half2 h3 = __floats2half2_rn(b.z, b.w);
        uint4 o;
        o.x = *(uint32_t*)&h0; o.y = *(uint32_t*)&h1;
        o.z = *(uint32_t*)&h2; o.w = *(uint32_t*)&h3;
        *(uint4*)(dst + i * 8) = o;
    }
}

// ================= fp16 mma GEMM (cp.async 3-stage, ldmatrix) ===============
// C[m][n] = sum_k A[m][k] * W[n][k]; 128x128 CTA tile, KSLAB=32 halves/slab.
// MODE 0: A=hx, scatter: Q/K fp32 into g_Q/g_K; V fp16 into g_Vt (transposed)
// MODE 1: A=hc, same with l = N_+n
// MODE 2: A=g_Oh, out[m][n] = acc + bias[n]  (fp32 out)
#define KSLAB  32
#define APADH  40                          // halves per smem row (80B, ldmatrix conflict-free)
#define STG_H  (128 * APADH)               // halves per matrix per stage (5120)
#define GEMM_SMEM (3 * 2 * STG_H * 2)      // 61440 bytes

template <int MODE>
__global__ __launch_bounds__(256, 2)
void gemm_h(const __half* __restrict__ A, const __half* __restrict__ W,
            const float* __restrict__ bias, float* __restrict__ out)
{
    constexpr int K = D_;
    constexpr int NS = K / KSLAB;          // 64 slabs
    extern __shared__ __half smh[];

    const int t = threadIdx.x;
    const int wid = t >> 5, lane = t & 31;
    const int g = lane >> 2, tig = lane & 3;
    const int wm = (wid >> 2) * 64;        // warp m offset (0/64)
    const int wn = (wid & 3) * 32;         // warp n offset
    const int n0 = blockIdx.x * 128;
    const int m0 = blockIdx.y * 128;

    // ldmatrix lane offsets
    const int a_ro = (lane & 7) + ((lane >> 3) & 1) * 8;
    const int a_co = ((lane >> 4) & 1) * 8;
    const int b_ro = (lane & 7) + ((lane >> 4) & 1) * 8;
    const int b_co = ((lane >> 3) & 1) * 8;

    // cp.async mapping: 512 tasks/matrix (128 rows x 4 chunks of 8 halves)
    const int rT = t >> 1;                 // row
    const int cT = (t & 1) * 2;            // first chunk (covers cT, cT+1)
    const __half* aRow = A + (size_t)(m0 + rT) * K + cT * 8;
    const __half* bRow = W + (size_t)(n0 + rT) * K + cT * 8;
    const uint32_t sbase = smem_u32(smh);

    float acc[4][4][4];
#pragma unroll
    for (int mi = 0; mi < 4; mi++)
#pragma unroll
        for (int ni = 0; ni < 4; ni++)
#pragma unroll
            for (int r = 0; r < 4; r++) acc[mi][ni][r] = 0.0f;

    auto issue = [&](int slab) {
        const int s = slab % 3;
        const uint32_t as = sbase + (uint32_t)(s * 2 * STG_H) * 2;
        const uint32_t bs = as + (uint32_t)STG_H * 2;
        const int ko = slab * KSLAB;
        const uint32_t soff = (uint32_t)(rT * APADH + cT * 8) * 2;
        cp16(as + soff,      aRow + ko);
        cp16(as + soff + 16, aRow + ko + 8);
        cp16(bs + soff,      bRow + ko);
        cp16(bs + soff + 16, bRow + ko + 8);
    };

    issue(0); CP_COMMIT();
    issue(1); CP_COMMIT();

    for (int kt = 0; kt < NS; kt++) {
        CP_WAIT1();
        __syncthreads();
        if (kt + 2 < NS) issue(kt + 2);
        CP_COMMIT();

        const uint32_t as_u = sbase + (uint32_t)((kt % 3) * 2 * STG_H) * 2;
        const uint32_t bs_u = as_u + (uint32_t)STG_H * 2;
#pragma unroll
        for (int ks = 0; ks < 2; ks++) {
            const int kb = ks * 16;
            uint32_t bf[4][2];
#pragma unroll
            for (int np = 0; np < 2; np++) {
                uint32_t r[4];
                ldmx4(r, bs_u + (uint32_t)((wn + np * 16 + b_ro) * APADH + kb + b_co) * 2);
                bf[2 * np][0] = r[0]; bf[2 * np][1] = r[1];
                bf[2 * np + 1][0] = r[2]; bf[2 * np + 1][1] = r[3];
            }
#pragma unroll
            for (int mi = 0; mi < 4; mi++) {
                uint32_t af[4];
                ldmx4(af, as_u + (uint32_t)((wm + mi * 16 + a_ro) * APADH + kb + a_co) * 2);
#pragma unroll
                for (int ni = 0; ni < 4; ni++)
                    mma_f16(acc[mi][ni], af, bf[ni]);
            }
        }
    }

    // -------- epilogue
    if (MODE == 0 || MODE == 1) {
        const int part = n0 >> 11;            // 0=q 1=k 2=v
        const int hh   = (n0 & 2047) >> 7;    // head
#pragma unroll
        for (int mi = 0; mi < 4; mi++) {
#pragma unroll
            for (int hi = 0; hi < 2; hi++) {
                const int m = m0 + wm + mi * 16 + g + hi * 8;
                int b, l;
                if (MODE == 0) { b = m >> 11; l = m & 2047; }
                else           { b = m >> 7;  l = N_ + (m & 127); }
                if (part < 2) {
                    float* dst = (part == 0) ? g_Q : g_K;
                    float* rowp = dst + ((size_t)(b * H_ + hh) * L_ + l) * DH_;
#pragma unroll
                    for (int ni = 0; ni < 4; ni++) {
                        const int dh = wn + ni * 8 + 2 * tig;
                        *(float2*)(rowp + dh) = make_float2(acc[mi][ni][hi * 2], acc[mi][ni][hi * 2 + 1]);
                    }
                } else {
                    __half* vb = g_Vt + (size_t)(b * H_ + hh) * DH_ * L_;
#pragma unroll
                    for (int ni = 0; ni < 4; ni++) {
                        const int dh = wn + ni * 8 + 2 * tig;
                        vb[(size_t)dh * L_ + l]       = __float2half(acc[mi][ni][hi * 2]);
                        vb[(size_t)(dh + 1) * L_ + l] = __float2half(acc[mi][ni][hi * 2 + 1]);
                    }
                }
            }
        }
    } else {
#pragma unroll
        for (int mi = 0; mi < 4; mi++) {
#pragma unroll
            for (int hi = 0; hi < 2; hi++) {
                const int m = m0 + wm + mi * 16 + g + hi * 8;
                float* op = out + (size_t)m * D_;
#pragma unroll
                for (int ni = 0; ni < 4; ni++) {
                    const int n = n0 + wn + ni * 8 + 2 * tig;
                    *(float2*)(op + n) = make_float2(acc[mi][ni][hi * 2] + bias[n],
                                                     acc[mi][ni][hi * 2 + 1] + bias[n + 1]);
                }
            }
        }
    }
}

// ---------------- RoPE table (fp64 trig, tiny) -------------------------------
__global__ void rope_table_k()
{
    const int l = blockIdx.x, i = threadIdx.x;   // i in [0,64)
    const float invf = (float)(1.0 / pow(10000.0, (double)i / 64.0));
    const float ang  = (float)l * invf;
    g_rope[l * 64 + i] = make_float2((float)cos((double)ang), (float)sin((double)ang));
}

// ---------------- L2-norm + scale + RoPE; warp per row, no smem --------------
__global__ __launch_bounds__(256)
void normrope_k(const float* __restrict__ scale, const float* __restrict__ cscale)
{
    const int wid = threadIdx.x >> 5, lane = threadIdx.x & 31;
    const int rg = blockIdx.x * 8 + wid;          // global row: b*H*L + h*L + l
    const int b = rg / (H_ * L_);
    const int rem = rg - b * (H_ * L_);
    const int h = rem / L_;
    const int l = rem - h * L_;

    const size_t rbase = (size_t)rg * DH_;
    const int c0 = lane * 4;
    const float* scp = (l < N_) ? scale : cscale;
    const float4 sc4 = *(const float4*)(scp + h * DH_ + c0);
    const float kmul = 45.25483399593904f;                 // sqrt(2048)
    const float qmul = kmul * 0.08838834764831845f;        // * 1/sqrt(128)

    const int i0 = c0 & 63;
    float cs[4], sn[4];
#pragma unroll
    for (int j = 0; j < 4; j++) {
        float2 rp = g_rope[l * 64 + i0 + j];
        cs[j] = rp.x; sn[j] = rp.y;
    }
    const bool lo = (lane < 16);

#pragma unroll
    for (int which = 0; which < 2; which++) {
        const float* ptr = ((which == 0) ? g_Q : g_K) + rbase;
        __half* hout = ((which == 0) ? g_Qh : g_Kh) + rbase;
        const float mul = (which == 0) ? qmul : kmul;

        float4 v4 = *(const float4*)(ptr + c0);
        float v[4] = {v4.x, v4.y, v4.z, v4.w};
        float ss = v[0] * v[0] + v[1] * v[1] + v[2] * v[2] + v[3] * v[3];
#pragma unroll
        for (int o = 16; o > 0; o >>= 1) ss += __shfl_xor_sync(0xffffffffu, ss, o);
        const float inv = 1.0f / fmaxf(sqrtf(ss), 1e-12f);

        float w[4];
        w[0] = v[0] * inv * sc4.x; w[1] = v[1] * inv * sc4.y;
        w[2] = v[2] * inv * sc4.z; w[3] = v[3] * inv * sc4.w;
        w[0] *= mul; w[1] *= mul; w[2] *= mul; w[3] *= mul;

        float o[4];
#pragma unroll
        for (int j = 0; j < 4; j++) {
            float p = __shfl_xor_sync(0xffffffffu, w[j], 16);
            o[j] = lo ? (w[j] * cs[j] - p * sn[j]) : (p * sn[j] + w[j] * cs[j]);
        }
        __half2 h0 = __floats2half2_rn(o[0], o[1]);
        __half2 h1 = __floats2half2_rn(o[2], o[3]);
        uint2 st; st.x = *(uint32_t*)&h0; st.y = *(uint32_t*)&h1;
        *(uint2*)(hout + c0) = st;
    }
}

// ---------------- flash attention, all-fp16 mma + ldmatrix -------------------
// CTA: 128 queries (8 warps x 16), key tiles of 64, double-buffered cp.async.
#define SKH  136                         // K smem row stride (halves, 272B ldmatrix-clean)
#define SVTH 72                          // Vt smem row stride (halves, 144B)
#define SPDH 72                          // P smem row stride (halves)
#define OFF_K   0                        // 2 x 64*136 halves
#define OFF_VT  (2 * 64 * SKH)           // 2 x 128*72 halves
#define OFF_P   (OFF_VT + 2 * 128 * SVTH)
#define ATT_HALVES (OFF_P + 8 * 16 * SPDH)
#define ATT_SMEM (ATT_HALVES * 2)        // 90112 bytes

__global__ __launch_bounds__(256)
void attn_h()
{
    extern __shared__ __half smh[];
    const int qt = blockIdx.x, h = blockIdx.y, b = blockIdx.z;
    const int t = threadIdx.x;
    const int wid = t >> 5, lane = t & 31;
    const int g = lane >> 2, tig = lane & 3;
    const int q0 = qt * 128, wrow = wid * 16;
    const size_t base = (size_t)(b * H_ + h) * L_ * DH_;
    const uint32_t sbase = smem_u32(smh);

    const int a_ro = (lane & 7) + ((lane >> 3) & 1) * 8;
    const int a_co = ((lane >> 4) & 1) * 8;
    const int b_ro = (lane & 7) + ((lane >> 4) & 1) * 8;
    const int b_co = ((lane >> 3) & 1) * 8;

    // ---- stage Q tile into (K-buffer region), load fragments
    {
        const __half* gq = g_Qh + base + (size_t)q0 * DH_;
#pragma unroll
        for (int ii = 0; ii < 8; ii++) {
            int idx = ii * 256 + t;
            int r = idx >> 4, c8 = (idx & 15) * 8;
            *(uint4*)(smh + r * SKH + c8) = *(const uint4*)(gq + (size_t)r * DH_ + c8);
        }
    }
    __syncthreads();
    uint32_t qf[8][4];
#pragma unroll
    for (int ks = 0; ks < 8; ks++)
        ldmx4(qf[ks], sbase + (uint32_t)((wrow + a_ro) * SKH + ks * 16 + a_co) * 2);
    __syncthreads();

    const __half* gk = g_Kh + base;
    const __half* gvt = g_Vt + (size_t)(b * H_ + h) * DH_ * L_;

    // cp.async fill of K and Vt tiles (buffer bb)
    auto issue = [&](int kt) {
        const int bb = kt & 1;
        const int k0 = kt * 64;
#pragma unroll
        for (int ii = 0; ii < 4; ii++) {
            int idx = ii * 256 + t;
            int r = idx >> 4, c8 = (idx & 15) * 8;
            cp16(sbase + (uint32_t)(OFF_K + bb * 64 * SKH + r * SKH + c8) * 2,
                 gk + (size_t)(k0 + r) * DH_ + c8);
        }
#pragma unroll
        for (int ii = 0; ii < 4; ii++) {
            int idx = ii * 256 + t;
            int dh = idx >> 3, c8 = (idx & 7) * 8;
            cp16(sbase + (uint32_t)(OFF_VT + bb * 128 * SVTH + dh * SVTH + c8) * 2,
                 gvt + (size_t)dh * L_ + k0 + c8);
        }
    };

    float acc[16][4];
#pragma unroll
    for (int nt = 0; nt < 16; nt++)
#pragma unroll
        for (int r = 0; r < 4; r++) acc[nt][r] = 0.0f;
    float m0 = -INFINITY, m1 = -INFINITY, l0 = 0.0f, l1 = 0.0f;

    const uint32_t Pw_u = sbase + (uint32_t)(OFF_P + wid * 16 * SPDH) * 2;
    __half* Pw = smh + OFF_P + wid * (16 * SPDH);

    issue(0); CP_COMMIT();

    constexpr int NT = L_ / 64;   // 34
    for (int kt = 0; kt < NT; kt++) {
        __syncthreads();
        if (kt + 1 < NT) issue(kt + 1);
        CP_COMMIT();
        CP_WAIT1();
        __syncthreads();

        const uint32_t sK_u = sbase + (uint32_t)(OFF_K + (kt & 1) * 64 * SKH) * 2;
        const uint32_t sVt_u = sbase + (uint32_t)(OFF_VT + (kt & 1) * 128 * SVTH) * 2;

        // ---- S = Q K^T
        float sfr[8][4];
#pragma unroll
        for (int nt = 0; nt < 8; nt++)
#pragma unroll
            for (int r = 0; r < 4; r++) sfr[nt][r] = 0.0f;
#pragma unroll
        for (int ks = 0; ks < 8; ks++) {
            const int kb = ks * 16;
            uint32_t kf[8][2];
#pragma unroll
            for (int np = 0; np < 4; np++) {
                uint32_t r[4];
                ldmx4(r, sK_u + (uint32_t)((np * 16 + b_ro) * SKH + kb + b_co) * 2);
                kf[2 * np][0] = r[0]; kf[2 * np][1] = r[1];
                kf[2 * np + 1][0] = r[2]; kf[2 * np + 1][1] = r[3];
            }
#pragma unroll
            for (int nt = 0; nt < 8; nt++)
                mma_f16(sfr[nt], qf[ks], kf[nt]);
        }

        // ---- online softmax (rows g and g+8)
        float mx0 = -INFINITY, mx1 = -INFINITY;
#pragma unroll
        for (int nt = 0; nt < 8; nt++) {
            mx0 = fmaxf(mx0, fmaxf(sfr[nt][0], sfr[nt][1]));
            mx1 = fmaxf(mx1, fmaxf(sfr[nt][2], sfr[nt][3]));
        }
        mx0 = fmaxf(mx0, __shfl_xor_sync(0xffffffffu, mx0, 1));
        mx0 = fmaxf(mx0, __shfl_xor_sync(0xffffffffu, mx0, 2));
        mx1 = fmaxf(mx1, __shfl_xor_sync(0xffffffffu, mx1, 1));
        mx1 = fmaxf(mx1, __shfl_xor_sync(0xffffffffu, mx1, 2));
        const float mn0 = fmaxf(m0, mx0), mn1 = fmaxf(m1, mx1);
        const float r0 = __expf(m0 - mn0), r1 = __expf(m1 - mn1);
        m0 = mn0; m1 = mn1;
        float s0 = 0.0f, s1 = 0.0f;
#pragma unroll
        for (int nt = 0; nt < 8; nt++) {
            float p00 = __expf(sfr[nt][0] - mn0);
            float p01 = __expf(sfr[nt][1] - mn0);
            float p10 = __expf(sfr[nt][2] - mn1);
            float p11 = __expf(sfr[nt][3] - mn1);
            s0 += p00 + p01; s1 += p10 + p11;
            *(__half2*)(Pw + g * SPDH + nt * 8 + 2 * tig) = __floats2half2_rn(p00, p01);
            *(__half2*)(Pw + (g + 8) * SPDH + nt * 8 + 2 * tig) = __floats2half2_rn(p10, p11);
        }
        s0 += __shfl_xor_sync(0xffffffffu, s0, 1);
        s0 += __shfl_xor_sync(0xffffffffu, s0, 2);
        s1 += __shfl_xor_sync(0xffffffffu, s1, 1);
        s1 += __shfl_xor_sync(0xffffffffu, s1, 2);
        l0 = l0 * r0 + s0;
        l1 = l1 * r1 + s1;
#pragma unroll
        for (int nt = 0; nt < 16; nt++) {
            acc[nt][0] *= r0; acc[nt][1] *= r0;
            acc[nt][2] *= r1; acc[nt][3] *= r1;
        }
        __syncwarp();

        // ---- PV: acc += P V   (V^T resident: b-frag rows are dh, cols keys)
#pragma unroll
        for (int ks = 0; ks < 4; ks++) {
            const int kb = ks * 16;
            uint32_t pf[4];
            ldmx4(pf, Pw_u + (uint32_t)(a_ro * SPDH + kb + a_co) * 2);
#pragma unroll
            for (int np = 0; np < 8; np++) {
                uint32_t r[4];
                ldmx4(r, sVt_u + (uint32_t)((np * 16 + b_ro) * SVTH + kb + b_co) * 2);
                mma_f16(acc[2 * np], pf, r);
                mma_f16(acc[2 * np + 1], pf, r + 2);
            }
        }
        __syncwarp();
    }

    // ---- epilogue (fp16 out)
    const float i0 = 1.0f / l0, i1 = 1.0f / l1;
    __half* o0 = g_Oh + ((size_t)b * N_ + q0 + wrow + g) * D_ + h * DH_;
    __half* o1 = g_Oh + ((size_t)b * N_ + q0 + wrow + g + 8) * D_ + h * DH_;
#pragma unroll
    for (int nt = 0; nt < 16; nt++) {
        const int col = nt * 8 + 2 * tig;
        *(__half2*)(o0 + col) = __floats2half2_rn(acc[nt][0] * i0, acc[nt][1] * i0);
        *(__half2*)(o1 + col) = __floats2half2_rn(acc[nt][2] * i1, acc[nt][3] * i1);
    }
}

// ---------------- launch -----------------------------------------------------
extern "C" void kernel_launch(void* const* d_in, const int* in_sizes, int n_in,
                              void* d_out, int out_size)
{
    const float* x    = (const float*)d_in[0];
    const float* c    = (const float*)d_in[1];
    const float* wqkv = (const float*)d_in[2];
    const float* wcq  = (const float*)d_in[3];
    const float* wo   = (const float*)d_in[4];
    const float* bo   = (const float*)d_in[5];
    const float* sc   = (const float*)d_in[6];
    const float* csc  = (const float*)d_in[7];
    float* out = (float*)d_out;

    cudaFuncSetAttribute(gemm_h<0>, cudaFuncAttributeMaxDynamicSharedMemorySize, GEMM_SMEM);
    cudaFuncSetAttribute(gemm_h<1>, cudaFuncAttributeMaxDynamicSharedMemorySize, GEMM_SMEM);
    cudaFuncSetAttribute(gemm_h<2>, cudaFuncAttributeMaxDynamicSharedMemorySize, GEMM_SMEM);
    cudaFuncSetAttribute(attn_h, cudaFuncAttributeMaxDynamicSharedMemorySize, ATT_SMEM);

    __half *hx, *hc, *hwqkv, *hwcq, *hwo, *oh;
    cudaGetSymbolAddress((void**)&hx, g_hx);
    cudaGetSymbolAddress((void**)&hc, g_hc);
    cudaGetSymbolAddress((void**)&hwqkv, g_hwqkv);
    cudaGetSymbolAddress((void**)&hwcq, g_hwcq);
    cudaGetSymbolAddress((void**)&hwo, g_hwo);
    cudaGetSymbolAddress((void**)&oh, g_Oh);

    // launches 1-5 (ncu -s 5 skips these), 6th = QKV GEMM gets profiled
    rope_table_k<<<L_, 64>>>();
    cvt_h<<<1024, 256>>>(x, hx, (B_ * N_ * D_) / 8);
    cvt_h<<<256, 256>>>(c, hc, (B_ * NC_ * D_) / 8);
    cvt_h<<<1024, 256>>>(wqkv, hwqkv, (D3_ * D_) / 8);
    cvt_h<<<1024, 256>>>(wcq, hwcq, (D3_ * D_) / 8);

    gemm_h<0><<<dim3(D3_ / 128, (B_ * N_) / 128), 256, GEMM_SMEM>>>(hx, hwqkv, nullptr, nullptr);
    gemm_h<1><<<dim3(D3_ / 128, (B_ * NC_) / 128), 256, GEMM_SMEM>>>(hc, hwcq, nullptr, nullptr);

    normrope_k<<<(B_ * H_ * L_) / 8, 256>>>(sc, csc);

    attn_h<<<dim3(N_ / 128, H_, B_), 256, ATT_SMEM>>>();

    cvt_h<<<1024, 256>>>(wo, hwo, (D_ * D_) / 8);
    gemm_h<2><<<dim3(D_ / 128, (B_ * N_) / 128), 256, GEMM_SMEM>>>(oh, hwo, bo, out);
}